// round 12
// baseline (speedup 1.0000x reference)
#include <cuda_runtime.h>
#include <cuda_bf16.h>
#include <math.h>
#include <stdint.h>
#include <string.h>

#define NTOK   2048
#define DMODEL 1024
#define NHEAD  16
#define DHEAD  64
#define FEXP   4096
#define NEXP   16
#define CAP    160      // int(1.25 * 2048 / 16)
#define HGRP   4        // heads per attention group

// ---------------------------------------------------------------------------
// Scratch (single __device__ bss array; aliased). ~123 MB total.
// ---------------------------------------------------------------------------
constexpr size_t SZ_ND = (size_t)NTOK * DMODEL * 4;            // 8 MB
constexpr size_t OFF_A    = 0;               // hln -> ctx
constexpr size_t OFF_B    = 1 * SZ_ND;       // x1
constexpr size_t OFF_C    = 2 * SZ_ND;       // h2
constexpr size_t OFF_D    = 3 * SZ_ND;       // (spare)
constexpr size_t OFF_E    = 4 * SZ_ND;       // q -> ye
constexpr size_t OFF_F    = 5 * SZ_ND;       // k
constexpr size_t OFF_G    = 6 * SZ_ND;       // v -> buf (spills 2.5MB into SC)
constexpr size_t OFF_SC   = 7 * SZ_ND;       // scores: HGRP x 16MB = 67MB
constexpr size_t SZ_SC    = (size_t)HGRP * NTOK * NTOK * 4;
constexpr size_t SZ_MAT   = (size_t)DMODEL * DMODEL;           // 1M elts
constexpr size_t OFF_HEXP = OFF_SC + (size_t)(4 << 20);        // clear of buf spill
constexpr size_t OFF_PAKW = OFF_HEXP;                          // 12 MB (dead before QK)
constexpr size_t OFF_WCMB = OFF_PAKW + 3 * SZ_MAT * 4;         // 12 MB combined weights
constexpr size_t OFF_PAKB = OFF_WCMB + 3 * SZ_MAT * 4;
constexpr size_t OFF_BCMB = OFF_PAKB + (size_t)3 * DMODEL * 4;
constexpr size_t OFF_ROUTES = OFF_SC + SZ_SC;
constexpr size_t OFF_SLOT   = OFF_ROUTES + (size_t)NTOK * 4;
constexpr size_t OFF_KEEP   = OFF_SLOT   + (size_t)NTOK * 4;
constexpr size_t OFF_PMAX   = OFF_KEEP   + (size_t)NTOK * 4;
constexpr size_t SCRATCH_BYTES = OFF_PMAX + (size_t)NTOK * 4;

__device__ __align__(256) unsigned char g_scratch[SCRATCH_BYTES];

// ---------------------------------------------------------------------------
// helpers
// ---------------------------------------------------------------------------
__device__ __forceinline__ void mma16816(float* c,
                                         uint32_t a0, uint32_t a1, uint32_t a2, uint32_t a3,
                                         uint32_t b0, uint32_t b1) {
    asm volatile(
        "mma.sync.aligned.m16n8k16.row.col.f32.bf16.bf16.f32 "
        "{%0,%1,%2,%3}, {%4,%5,%6,%7}, {%8,%9}, {%0,%1,%2,%3};"
        : "+f"(c[0]), "+f"(c[1]), "+f"(c[2]), "+f"(c[3])
        : "r"(a0), "r"(a1), "r"(a2), "r"(a3), "r"(b0), "r"(b1));
}

__device__ __forceinline__ void ldsm_x4(uint32_t* r, uint32_t saddr) {
    asm volatile("ldmatrix.sync.aligned.m8n8.x4.shared.b16 {%0,%1,%2,%3}, [%4];"
        : "=r"(r[0]), "=r"(r[1]), "=r"(r[2]), "=r"(r[3]) : "r"(saddr));
}
__device__ __forceinline__ void ldsm_x2(uint32_t* r, uint32_t saddr) {
    asm volatile("ldmatrix.sync.aligned.m8n8.x2.shared.b16 {%0,%1}, [%2];"
        : "=r"(r[0]), "=r"(r[1]) : "r"(saddr));
}

__device__ __forceinline__ uint32_t bf162_bits(float l0, float l1) {
    __nv_bfloat162 p = __floats2bfloat162_rn(l0, l1);
    uint32_t u;
    memcpy(&u, &p, 4);
    return u;
}

// ---------------------------------------------------------------------------
// HMMA GEMM (bf16 trunc-split-2, fp32 accumulate), mma.sync + ldmatrix.
//   C[m,n] = sum_k A[m,k]*B[n,k]  (B K-major)   TRB: B global [K,Nd] row-major
//   BM in {160,128,64}; BK=32; BN in {64,128}. 256 thr = 8 warps, 1 CTA/SM.
// ---------------------------------------------------------------------------
template<int BM, int BN, bool TRB, bool BIAS, bool RELU, bool RESID, bool MASKSCALE, bool CTRIM>
__global__ void __launch_bounds__(256, 1) mma_gemm(
    const float* __restrict__ A, const float* __restrict__ B,
    const float* __restrict__ bias, const float* __restrict__ resid,
    float* __restrict__ C,
    int M, int Nd, int K, int lda, int ldb, int ldc,
    long long sA, long long sB, long long sC, long long sBias)
{
    constexpr int BK = 32;
    constexpr int STR = 80;                 // bytes per smem row (32 bf16 + pad)
    constexpr int WMW = (BM >= 128) ? 2 : 1;
    constexpr int MT  = BM / (WMW * 16);
    constexpr int WNW = 8 / WMW;
    constexpr int WNSZ = BN / WNW;
    constexpr int NT  = WNSZ / 8;
    constexpr int NA4 = BM / 32;
    constexpr int NB4 = BN / 32;
    constexpr int BUFB = (2 * BM + 2 * BN) * STR;

    extern __shared__ unsigned char dsm[];

    const int tid = threadIdx.x;
    const int wid = tid >> 5, lane = tid & 31;
    const int wm = (WMW == 2) ? (wid & 1) : 0;
    const int wn = (WMW == 2) ? (wid >> 1) : wid;
    const int gid = lane >> 2, tig = lane & 3;
    const uint32_t dsm_s = (uint32_t)__cvta_generic_to_shared(dsm);
    const uint32_t laneA = (uint32_t)((lane & 15) * STR + (lane >> 4) * 16);
    const uint32_t laneB = (uint32_t)((lane & 7) * STR + ((lane >> 3) & 1) * 16);

    A += (long long)blockIdx.z * sA;
    B += (long long)blockIdx.z * sB;
    C += (long long)blockIdx.z * sC;
    const float* bptr = nullptr;
    if (BIAS) bptr = bias + (long long)blockIdx.z * sBias;

    const int m0 = blockIdx.y * BM;
    const int n0 = blockIdx.x * BN;

    if (MASKSCALE) {
        int hardLim = (m0 + BM + 255) & ~255;   // beyond triangular-softmax reads
        if (n0 >= hardLim) return;
        if (n0 > m0 + BM - 1) {   // fully masked tile: fill -inf, skip compute
            for (int i = tid; i < BM * BN / 4; i += 256) {
                int r = i / (BN / 4), c = (i % (BN / 4)) * 4;
                if (m0 + r < M)
                    *(float4*)&C[(long long)(m0 + r) * ldc + n0 + c] =
                        make_float4(-INFINITY, -INFINITY, -INFINITY, -INFINITY);
            }
            return;
        }
    }

    float acc[MT][NT][4];
    #pragma unroll
    for (int i = 0; i < MT; i++)
        #pragma unroll
        for (int j = 0; j < NT; j++)
            #pragma unroll
            for (int l = 0; l < 4; l++) acc[i][j][l] = 0.f;

    float4 aS[NA4], bS[NB4];

    auto ldA = [&](int k0) {
        #pragma unroll
        for (int i = 0; i < NA4; i++) {
            int j = tid + i * 256;
            int r = j >> 3, c = (j & 7) * 4;
            aS[i] = (m0 + r < M) ? *(const float4*)&A[(long long)(m0 + r) * lda + k0 + c]
                                 : make_float4(0.f, 0.f, 0.f, 0.f);
        }
    };
    auto ldB = [&](int k0) {
        if (!TRB) {
            #pragma unroll
            for (int i = 0; i < NB4; i++) {
                int j = tid + i * 256;
                int r = j >> 3, c = (j & 7) * 4;
                bS[i] = (n0 + r < Nd) ? *(const float4*)&B[(long long)(n0 + r) * ldb + k0 + c]
                                      : make_float4(0.f, 0.f, 0.f, 0.f);
            }
        } else {
            #pragma unroll
            for (int i = 0; i < NB4; i++) {
                int j = tid + i * 256;
                int r = j / (BN / 4), c = (j % (BN / 4)) * 4;
                bS[i] = *(const float4*)&B[(long long)(k0 + r) * ldb + n0 + c];
            }
        }
    };
    auto stA = [&](unsigned char* bufb) {
        unsigned char* Ah = bufb;
        unsigned char* Al = bufb + BM * STR;
        #pragma unroll
        for (int i = 0; i < NA4; i++) {
            int j = tid + i * 256;
            int r = j >> 3, c4 = j & 7;
            uint4 u;
            memcpy(&u, &aS[i], 16);
            uint32_t h01 = __byte_perm(u.x, u.y, 0x7632);
            uint32_t h23 = __byte_perm(u.z, u.w, 0x7632);
            float l0 = aS[i].x - __uint_as_float(u.x & 0xffff0000u);
            float l1 = aS[i].y - __uint_as_float(u.y & 0xffff0000u);
            float l2 = aS[i].z - __uint_as_float(u.z & 0xffff0000u);
            float l3 = aS[i].w - __uint_as_float(u.w & 0xffff0000u);
            uint32_t off = (uint32_t)(r * STR + c4 * 8);
            *(uint2*)(Ah + off) = make_uint2(h01, h23);
            *(uint2*)(Al + off) = make_uint2(bf162_bits(l0, l1), bf162_bits(l2, l3));
        }
    };
    auto stB = [&](unsigned char* bufb) {
        unsigned char* Bh = bufb + 2 * BM * STR;
        unsigned char* Bl = bufb + 2 * BM * STR + BN * STR;
        if (!TRB) {
            #pragma unroll
            for (int i = 0; i < NB4; i++) {
                int j = tid + i * 256;
                int r = j >> 3, c4 = j & 7;
                uint4 u;
                memcpy(&u, &bS[i], 16);
                uint32_t h01 = __byte_perm(u.x, u.y, 0x7632);
                uint32_t h23 = __byte_perm(u.z, u.w, 0x7632);
                float l0 = bS[i].x - __uint_as_float(u.x & 0xffff0000u);
                float l1 = bS[i].y - __uint_as_float(u.y & 0xffff0000u);
                float l2 = bS[i].z - __uint_as_float(u.z & 0xffff0000u);
                float l3 = bS[i].w - __uint_as_float(u.w & 0xffff0000u);
                uint32_t off = (uint32_t)(r * STR + c4 * 8);
                *(uint2*)(Bh + off) = make_uint2(h01, h23);
                *(uint2*)(Bl + off) = make_uint2(bf162_bits(l0, l1), bf162_bits(l2, l3));
            }
        } else {
            #pragma unroll
            for (int i = 0; i < NB4; i++) {
                int j = tid + i * 256;
                int r = j / (BN / 4), c4 = j % (BN / 4);
                float v[4] = {bS[i].x, bS[i].y, bS[i].z, bS[i].w};
                #pragma unroll
                for (int q = 0; q < 4; q++) {
                    int n = c4 * 4 + q;
                    uint32_t ub = __float_as_uint(v[q]);
                    unsigned short h = (unsigned short)(ub >> 16);
                    float lof = v[q] - __uint_as_float(ub & 0xffff0000u);
                    unsigned short l = __bfloat16_as_ushort(__float2bfloat16_rn(lof));
                    uint32_t off = (uint32_t)(n * STR + r * 2);
                    *(unsigned short*)(Bh + off) = h;
                    *(unsigned short*)(Bl + off) = l;
                }
            }
        }
    };

    auto compute = [&](uint32_t bufo) {
        const uint32_t AhS = dsm_s + bufo;
        const uint32_t AlS = AhS + BM * STR;
        const uint32_t BhS = dsm_s + bufo + 2 * BM * STR;
        const uint32_t BlS = BhS + BN * STR;
        #pragma unroll
        for (int ks = 0; ks < 2; ks++) {
            const uint32_t kb = (uint32_t)(ks * 32);
            uint32_t a[MT][4], b[NT][2], bl[NT][2];
            #pragma unroll
            for (int ms = 0; ms < MT; ms++)
                ldsm_x4(a[ms], AhS + (uint32_t)((wm * (MT * 16) + ms * 16) * STR) + kb + laneA);
            #pragma unroll
            for (int ns = 0; ns < NT; ns++) {
                uint32_t bo = (uint32_t)((wn * WNSZ + ns * 8) * STR) + kb + laneB;
                ldsm_x2(b[ns],  BhS + bo);
                ldsm_x2(bl[ns], BlS + bo);
            }
            #pragma unroll
            for (int ms = 0; ms < MT; ms++)
                #pragma unroll
                for (int ns = 0; ns < NT; ns++)
                    mma16816(acc[ms][ns], a[ms][0], a[ms][1], a[ms][2], a[ms][3],
                             b[ns][0], b[ns][1]);
            #pragma unroll
            for (int ms = 0; ms < MT; ms++)
                #pragma unroll
                for (int ns = 0; ns < NT; ns++)
                    mma16816(acc[ms][ns], a[ms][0], a[ms][1], a[ms][2], a[ms][3],
                             bl[ns][0], bl[ns][1]);
            #pragma unroll
            for (int ms = 0; ms < MT; ms++)
                ldsm_x4(a[ms], AlS + (uint32_t)((wm * (MT * 16) + ms * 16) * STR) + kb + laneA);
            #pragma unroll
            for (int ms = 0; ms < MT; ms++)
                #pragma unroll
                for (int ns = 0; ns < NT; ns++)
                    mma16816(acc[ms][ns], a[ms][0], a[ms][1], a[ms][2], a[ms][3],
                             b[ns][0], b[ns][1]);
        }
    };

    int nch = K >> 5;
    if (CTRIM) { int lim = (m0 + BM) >> 5; nch = nch < lim ? nch : lim; }

    ldA(0); ldB(0);
    stA(dsm); stB(dsm);
    __syncthreads();
    for (int c = 0; c < nch; c++) {
        if (c + 1 < nch) { ldA((c + 1) << 5); ldB((c + 1) << 5); }
        compute((uint32_t)((c & 1) * BUFB));
        if (c + 1 < nch) {
            unsigned char* nb = dsm + ((c + 1) & 1) * BUFB;
            stA(nb); stB(nb);
        }
        __syncthreads();
    }

    // ---- epilogue: direct stores from accumulators
    #pragma unroll
    for (int ms = 0; ms < MT; ms++) {
        #pragma unroll
        for (int ns = 0; ns < NT; ns++) {
            int m = m0 + wm * (MT * 16) + ms * 16 + gid;
            int n = n0 + wn * WNSZ + ns * 8 + tig * 2;
            float* cp = acc[ms][ns];
            #pragma unroll
            for (int half = 0; half < 2; half++) {
                int mm = m + half * 8;
                if (mm >= M) continue;
                float v0 = cp[half * 2 + 0], v1 = cp[half * 2 + 1];
                if (BIAS) { v0 += bptr[n]; v1 += bptr[n + 1]; }
                if (MASKSCALE) {
                    v0 *= 0.125f; v1 *= 0.125f;
                    if (n > mm) v0 = -INFINITY;
                    if (n + 1 > mm) v1 = -INFINITY;
                }
                if (RELU) { v0 = fmaxf(v0, 0.f); v1 = fmaxf(v1, 0.f); }
                if (RESID) {
                    float2 rr = *(const float2*)&resid[(long long)mm * ldc + n];
                    v0 += rr.x; v1 += rr.y;
                }
                *(float2*)&C[(long long)mm * ldc + n] = make_float2(v0, v1);
            }
        }
    }
}

// ---------------------------------------------------------------------------
// Pack wk|wq|wv and bk|bq|bv into contiguous scratch
// ---------------------------------------------------------------------------
__global__ void __launch_bounds__(256) pack3_k(
    const float* __restrict__ a0, const float* __restrict__ a1, const float* __restrict__ a2,
    const float* __restrict__ b0, const float* __restrict__ b1, const float* __restrict__ b2,
    float* __restrict__ w, float* __restrict__ b)
{
    constexpr int N4 = DMODEL * DMODEL / 4;
    int idx = blockIdx.x * 256 + threadIdx.x;
    if (idx < 3 * N4) {
        const float* src = (idx < N4) ? a0 : (idx < 2 * N4) ? a1 : a2;
        int loc = idx - (idx < N4 ? 0 : (idx < 2 * N4 ? N4 : 2 * N4));
        ((float4*)w)[idx] = ((const float4*)src)[loc];
    }
    if (idx < 3 * DMODEL / 4) {
        constexpr int B4 = DMODEL / 4;
        const float* src = (idx < B4) ? b0 : (idx < 2 * B4) ? b1 : b2;
        int loc = idx - (idx < B4 ? 0 : (idx < 2 * B4 ? B4 : 2 * B4));
        ((float4*)b)[idx] = ((const float4*)src)[loc];
    }
}

// ---------------------------------------------------------------------------
// biascomb: bcomb[z*D+i] = ipb[z*D+i] + dot(ipw_z[i,:], pakb_z)
// One warp per output element; grid 384 x 256 = 3072 warps.
// ---------------------------------------------------------------------------
__global__ void __launch_bounds__(256) biascomb_k(
    const float* __restrict__ ipw, const float* __restrict__ ipb,
    const float* __restrict__ pakb, float* __restrict__ bcomb)
{
    int gw = (blockIdx.x * 256 + threadIdx.x) >> 5;
    int lane = threadIdx.x & 31;
    if (gw >= 3 * DMODEL) return;
    int z = gw >> 10, i = gw & (DMODEL - 1);
    const float* wrow = ipw + ((size_t)z * DMODEL + i) * DMODEL;
    const float* bz = pakb + z * DMODEL;
    float s = 0.f;
    for (int k2 = lane; k2 < DMODEL; k2 += 32) s += wrow[k2] * bz[k2];
    #pragma unroll
    for (int o = 16; o; o >>= 1) s += __shfl_down_sync(0xffffffffu, s, o);
    if (lane == 0) bcomb[gw] = s + ipb[gw];
}

// ---------------------------------------------------------------------------
// Block reductions + glue kernels
// ---------------------------------------------------------------------------
__device__ __forceinline__ float blockReduceSum(float val, float* red) {
    int lane = threadIdx.x & 31, wid = threadIdx.x >> 5;
    #pragma unroll
    for (int o = 16; o; o >>= 1) val += __shfl_down_sync(0xffffffffu, val, o);
    __syncthreads();
    if (lane == 0) red[wid] = val;
    __syncthreads();
    if (threadIdx.x < 32) {
        val = (lane < 8) ? red[lane] : 0.f;
        #pragma unroll
        for (int o = 4; o; o >>= 1) val += __shfl_down_sync(0xffffffffu, val, o);
        if (lane == 0) red[0] = val;
    }
    __syncthreads();
    return red[0];
}
__device__ __forceinline__ float blockReduceMax(float val, float* red) {
    int lane = threadIdx.x & 31, wid = threadIdx.x >> 5;
    #pragma unroll
    for (int o = 16; o; o >>= 1) val = fmaxf(val, __shfl_down_sync(0xffffffffu, val, o));
    __syncthreads();
    if (lane == 0) red[wid] = val;
    __syncthreads();
    if (threadIdx.x < 32) {
        val = (lane < 8) ? red[lane] : -INFINITY;
        #pragma unroll
        for (int o = 4; o; o >>= 1) val = fmaxf(val, __shfl_down_sync(0xffffffffu, val, o));
        if (lane == 0) red[0] = val;
    }
    __syncthreads();
    return red[0];
}

__global__ void __launch_bounds__(256) ln_k(const float* __restrict__ x,
                                            const float* __restrict__ w,
                                            const float* __restrict__ b,
                                            float* __restrict__ out) {
    __shared__ float red[8];
    int row = blockIdx.x, tid = threadIdx.x;
    const float* xr = x + (size_t)row * DMODEL;
    float v[4];
    float s = 0.f;
    #pragma unroll
    for (int i = 0; i < 4; i++) { v[i] = xr[tid + i * 256]; s += v[i]; }
    s = blockReduceSum(s, red);
    float mu = s * (1.f / DMODEL);
    float s2 = 0.f;
    #pragma unroll
    for (int i = 0; i < 4; i++) { float d = v[i] - mu; s2 += d * d; }
    s2 = blockReduceSum(s2, red);
    float rstd = rsqrtf(s2 * (1.f / DMODEL) + 1e-5f);
    float* orow = out + (size_t)row * DMODEL;
    #pragma unroll
    for (int i = 0; i < 4; i++) {
        int c = tid + i * 256;
        orow[c] = (v[i] - mu) * rstd * w[c] + b[c];
    }
}

// Triangular softmax: row r only processes ceil((r+1)/256)*256 columns.
__global__ void __launch_bounds__(256) softmax_k(float* __restrict__ S) {
    __shared__ float red[8];
    int r = blockIdx.x & (NTOK - 1);
    float* row = S + (long long)blockIdx.x * NTOK;
    int tid = threadIdx.x;
    int nit = (r >> 8) + 1;
    float v[8];
    float mx = -INFINITY;
    #pragma unroll
    for (int i = 0; i < 8; i++) {
        if (i < nit) { v[i] = row[tid + i * 256]; mx = fmaxf(mx, v[i]); }
    }
    mx = blockReduceMax(mx, red);
    float s = 0.f;
    #pragma unroll
    for (int i = 0; i < 8; i++) {
        if (i < nit) { v[i] = expf(v[i] - mx); s += v[i]; }
    }
    s = blockReduceSum(s, red);
    float inv = 1.f / s;
    #pragma unroll
    for (int i = 0; i < 8; i++) {
        if (i < nit) row[tid + i * 256] = v[i] * inv;
    }
}

__global__ void __launch_bounds__(512) router_k(const float* __restrict__ h,
                                                const float* __restrict__ rw,
                                                const float* __restrict__ rb,
                                                int* __restrict__ routes,
                                                float* __restrict__ pmax) {
    __shared__ float lg[NEXP];
    int t = blockIdx.x;
    int wid = threadIdx.x >> 5, lane = threadIdx.x & 31;
    const float* hr = h + (size_t)t * DMODEL;
    const float* wr = rw + (size_t)wid * DMODEL;
    float s = 0.f;
    for (int k = lane; k < DMODEL; k += 32) s += hr[k] * wr[k];
    #pragma unroll
    for (int o = 16; o; o >>= 1) s += __shfl_down_sync(0xffffffffu, s, o);
    if (lane == 0) lg[wid] = s + rb[wid];
    __syncthreads();
    if (threadIdx.x == 0) {
        float mx = lg[0]; int arg = 0;
        #pragma unroll
        for (int e = 1; e < NEXP; e++)
            if (lg[e] > mx) { mx = lg[e]; arg = e; }
        float sum = 0.f;
        #pragma unroll
        for (int e = 0; e < NEXP; e++) sum += expf(lg[e] - mx);
        routes[t] = arg;
        pmax[t] = 1.f / sum;
    }
}

__global__ void __launch_bounds__(512) slot_k(const int* __restrict__ routes,
                                              int* __restrict__ slot,
                                              int* __restrict__ keep) {
    __shared__ int sr[NTOK];
    int tid = threadIdx.x;
    for (int i = tid; i < NTOK; i += 512) sr[i] = routes[i];
    __syncthreads();
    int wid = tid >> 5, lane = tid & 31;
    int pos = 0;
    unsigned lmask = (1u << lane) - 1u;
    for (int base = 0; base < NTOK; base += 32) {
        int r = sr[base + lane];
        unsigned m = __ballot_sync(0xffffffffu, r == wid);
        if (r == wid) {
            int p = pos + __popc(m & lmask);
            int kp = (p < CAP) ? 1 : 0;
            keep[base + lane] = kp;
            slot[base + lane] = kp ? (wid * CAP + p) : (NEXP * CAP);
        }
        pos += __popc(m);
    }
}

__global__ void __launch_bounds__(256) gather_k(const float* __restrict__ h,
                                                const int* __restrict__ slot,
                                                const int* __restrict__ keep,
                                                float* __restrict__ buf) {
    int t = blockIdx.x;
    if (!keep[t]) return;
    int s = slot[t];
    const float4* src = (const float4*)(h + (size_t)t * DMODEL);
    float4* dst = (float4*)(buf + (size_t)s * DMODEL);
    dst[threadIdx.x] = src[threadIdx.x];
}

__global__ void __launch_bounds__(256) final_k(const float* __restrict__ x1,
                                               const float* __restrict__ h2,
                                               const float* __restrict__ ye,
                                               const int* __restrict__ slot,
                                               const int* __restrict__ keep,
                                               const float* __restrict__ pmax,
                                               float* __restrict__ out) {
    int t = blockIdx.x;
    float p = pmax[t];
    const float4* ysrc = keep[t]
        ? (const float4*)(ye + (size_t)slot[t] * DMODEL)
        : (const float4*)(h2 + (size_t)t * DMODEL);
    const float4* xs = (const float4*)(x1 + (size_t)t * DMODEL);
    float4 a = xs[threadIdx.x];
    float4 y = ysrc[threadIdx.x];
    float4 o = make_float4(a.x + y.x * p, a.y + y.y * p, a.z + y.z * p, a.w + y.w * p);
    ((float4*)out)[(size_t)t * (DMODEL / 4) + threadIdx.x] = o;
}

// ---------------------------------------------------------------------------
// Launch
// ---------------------------------------------------------------------------
extern "C" void kernel_launch(void* const* d_in, const int* in_sizes, int n_in,
                              void* d_out, int out_size) {
    const float* x    = (const float*)d_in[0];
    const float* wk   = (const float*)d_in[1];
    const float* bk   = (const float*)d_in[2];
    const float* wq   = (const float*)d_in[3];
    const float* bq   = (const float*)d_in[4];
    const float* wv   = (const float*)d_in[5];
    const float* bv   = (const float*)d_in[6];
    const float* ipw  = (const float*)d_in[7];
    const float* ipb  = (const float*)d_in[8];
    const float* opw  = (const float*)d_in[9];
    const float* opb  = (const float*)d_in[10];
    const float* ln1w = (const float*)d_in[11];
    const float* ln1b = (const float*)d_in[12];
    const float* ln2w = (const float*)d_in[13];
    const float* ln2b = (const float*)d_in[14];
    const float* rw   = (const float*)d_in[15];
    const float* rb   = (const float*)d_in[16];
    const float* w1   = (const float*)d_in[17];
    const float* b1   = (const float*)d_in[18];
    const float* w2   = (const float*)d_in[19];
    const float* b2   = (const float*)d_in[20];
    float* out = (float*)d_out;

    void* sp = nullptr;
    cudaGetSymbolAddress(&sp, g_scratch);
    char* base = (char*)sp;
    float* hln    = (float*)(base + OFF_A);
    float* ctx    = (float*)(base + OFF_A);
    float* x1     = (float*)(base + OFF_B);
    float* h2     = (float*)(base + OFF_C);
    float* q      = (float*)(base + OFF_E);
    float* ye     = (float*)(base + OFF_E);
    float* k      = (float*)(base + OFF_F);
    float* v      = (float*)(base + OFF_G);
    float* buf    = (float*)(base + OFF_G);
    float* sc     = (float*)(base + OFF_SC);
    float* hexp   = (float*)(base + OFF_HEXP);
    float* pakw   = (float*)(base + OFF_PAKW);
    float* wcmb   = (float*)(base + OFF_WCMB);
    float* pakb   = (float*)(base + OFF_PAKB);
    float* bcmb   = (float*)(base + OFF_BCMB);
    int*   routes = (int*)(base + OFF_ROUTES);
    int*   slot   = (int*)(base + OFF_SLOT);
    int*   keep   = (int*)(base + OFF_KEEP);
    float* pmax   = (float*)(base + OFF_PMAX);

    constexpr long long MAT = (long long)DMODEL * DMODEL;     // 1M

    // instantiations + dynamic smem opt-in (round-11 configs + TRB combine)
    auto GP   = mma_gemm<128, 128, false, true,  false, false, false, false>;  // fused proj
    auto GCMB = mma_gemm<128, 128, true,  false, false, false, false, false>;  // weight combine
    auto GPR  = mma_gemm<128, 128, false, true,  false, true,  false, false>;  // out-proj+resid
    auto GQK  = mma_gemm<128, 128, false, false, false, false, true,  false>;  // QK^T masked
    auto GPV  = mma_gemm<64,  64,  true,  false, false, false, false, true >;  // P@V causal-trim
    auto GW1  = mma_gemm<160, 128, false, true,  true,  false, false, false>;  // w1+relu
    auto GW2  = mma_gemm<160, 128, false, true,  false, false, false, false>;  // w2
    constexpr int SM128 = 2 * (2 * 128 + 2 * 128) * 80;   // 81920
    constexpr int SM64  = 2 * (2 * 64  + 2 * 64)  * 80;   // 40960
    constexpr int SM160 = 2 * (2 * 160 + 2 * 128) * 80;   // 92160
    cudaFuncSetAttribute(GP,   cudaFuncAttributeMaxDynamicSharedMemorySize, SM128);
    cudaFuncSetAttribute(GCMB, cudaFuncAttributeMaxDynamicSharedMemorySize, SM128);
    cudaFuncSetAttribute(GPR,  cudaFuncAttributeMaxDynamicSharedMemorySize, SM128);
    cudaFuncSetAttribute(GQK,  cudaFuncAttributeMaxDynamicSharedMemorySize, SM128);
    cudaFuncSetAttribute(GPV,  cudaFuncAttributeMaxDynamicSharedMemorySize, SM64);
    cudaFuncSetAttribute(GW1,  cudaFuncAttributeMaxDynamicSharedMemorySize, SM160);
    cudaFuncSetAttribute(GW2,  cudaFuncAttributeMaxDynamicSharedMemorySize, SM160);

    // ---- LN1 + weight packing + weight combine (weight-only work)
    ln_k<<<NTOK, 256>>>(x, ln1w, ln1b, hln);
    pack3_k<<<(3 * DMODEL * DMODEL / 4 + 255) / 256, 256>>>(
        wk, wq, wv, bk, bq, bv, pakw, pakb);
    // Wcomb_z = ipw_z @ w_z   (TRB: B row-major [K, Nd])
    dim3 gC(DMODEL / 128, DMODEL / 128, 3);
    GCMB<<<gC, 256, SM128>>>(ipw, pakw, nullptr, nullptr, wcmb,
        DMODEL, DMODEL, DMODEL, DMODEL, DMODEL, DMODEL,
        MAT, MAT, MAT, 0);
    biascomb_k<<<384, 256>>>(ipw, ipb, pakb, bcmb);

    // ---- fused projection: q|k|v = hln @ Wcomb^T + bcomb  (one z=3 launch)
    //      (swapped K/Q per reference: z order wk,wq,wv -> q,k,v)
    dim3 gD3(DMODEL / 128, NTOK / 128, 3);
    GP<<<gD3, 256, SM128>>>(hln, wcmb, bcmb, nullptr, q,
        NTOK, DMODEL, DMODEL, DMODEL, DMODEL, DMODEL,
        0, MAT, (long long)NTOK * DMODEL, DMODEL);

    // ---- attention: groups of HGRP heads, z-batched
    for (int g = 0; g < NHEAD / HGRP; g++) {
        const int ho = g * HGRP * DHEAD;
        dim3 gS(NTOK / 128, NTOK / 128, HGRP);
        GQK<<<gS, 256, SM128>>>(q + ho, k + ho, nullptr, nullptr, sc,
            NTOK, NTOK, DHEAD, DMODEL, DMODEL, NTOK,
            DHEAD, DHEAD, (long long)NTOK * NTOK, 0);
        softmax_k<<<HGRP * NTOK, 256>>>(sc);
        dim3 gV(1, NTOK / 64, HGRP);
        GPV<<<gV, 256, SM64>>>(sc, v + ho, nullptr, nullptr, ctx + ho,
            NTOK, DHEAD, NTOK, NTOK, DMODEL, DMODEL,
            (long long)NTOK * NTOK, DHEAD, DHEAD, 0);
    }

    // ---- x1 = x + ctx @ opw^T + opb
    dim3 gD(DMODEL / 128, NTOK / 128, 1);
    GPR<<<gD, 256, SM128>>>(ctx, opw, opb, x, x1,
        NTOK, DMODEL, DMODEL, DMODEL, DMODEL, DMODEL, 0, 0, 0, 0);

    // ---- LN2
    ln_k<<<NTOK, 256>>>(x1, ln2w, ln2b, h2);

    // ---- router + routing + gather
    router_k<<<NTOK, 512>>>(h2, rw, rb, routes, pmax);
    slot_k<<<1, 512>>>(routes, slot, keep);
    gather_k<<<NTOK, 256>>>(h2, slot, keep, buf);

    // ---- expert FFN layer 1 (relu): single BM=160 launch
    dim3 g1(FEXP / 128, 1, NEXP);
    GW1<<<g1, 256, SM160>>>(buf, w1, b1, nullptr, hexp,
        CAP, FEXP, DMODEL, DMODEL, DMODEL, FEXP,
        (long long)CAP * DMODEL, (long long)FEXP * DMODEL,
        (long long)CAP * FEXP, FEXP);

    // ---- expert FFN layer 2: single BM=160 launch
    dim3 g2(DMODEL / 128, 1, NEXP);
    GW2<<<g2, 256, SM160>>>(hexp, w2, b2, nullptr, ye,
        CAP, DMODEL, FEXP, FEXP, FEXP, DMODEL,
        (long long)CAP * FEXP, (long long)DMODEL * FEXP,
        (long long)CAP * DMODEL, DMODEL);

    // ---- final combine
    final_k<<<NTOK, 256>>>(x1, h2, ye, slot, keep, pmax, out);
}

// round 14
// speedup vs baseline: 1.0489x; 1.0489x over previous
#include <cuda_runtime.h>
#include <cuda_bf16.h>
#include <math.h>
#include <stdint.h>
#include <string.h>

#define NTOK   2048
#define DMODEL 1024
#define NHEAD  16
#define DHEAD  64
#define FEXP   4096
#define NEXP   16
#define CAP    160      // int(1.25 * 2048 / 16)
#define HGRP   4        // heads per attention group

// ---------------------------------------------------------------------------
// Scratch (single __device__ bss array; aliased). ~147 MB total.
// ---------------------------------------------------------------------------
constexpr size_t SZ_ND = (size_t)NTOK * DMODEL * 4;            // 8 MB
constexpr size_t OFF_A    = 0;               // hln -> ctx
constexpr size_t OFF_B    = 1 * SZ_ND;       // qin -> x1
constexpr size_t OFF_C    = 2 * SZ_ND;       // kin -> h2
constexpr size_t OFF_D    = 3 * SZ_ND;       // vin -> PV split partials (4MB)
constexpr size_t OFF_E    = 4 * SZ_ND;       // q -> ye
constexpr size_t OFF_F    = 5 * SZ_ND;       // k
constexpr size_t OFF_G    = 6 * SZ_ND;       // v -> buf (spills 2.5MB into SC)
constexpr size_t OFF_SC   = 7 * SZ_ND;       // scores: HGRP x 16MB = 64MiB
constexpr size_t SZ_SC    = (size_t)HGRP * NTOK * NTOK * 4;
constexpr size_t OFF_HEXP = OFF_SC + (size_t)(4 << 20);        // 42MB, clear of buf spill
constexpr size_t OFF_PAKW = OFF_HEXP;                          // 12 MB (pack region)
constexpr size_t OFF_PAKB = OFF_PAKW + (size_t)3 * DMODEL * DMODEL * 4;
constexpr size_t OFF_ROUTES = OFF_SC + SZ_SC;
constexpr size_t OFF_SLOT   = OFF_ROUTES + (size_t)NTOK * 4;
constexpr size_t OFF_KEEP   = OFF_SLOT   + (size_t)NTOK * 4;
constexpr size_t OFF_PMAX   = OFF_KEEP   + (size_t)NTOK * 4;
// dedicated w2 split-K partials region (2 x 10.5MB) at scratch end
constexpr size_t OFF_W2P  = OFF_PMAX + (size_t)NTOK * 4;
constexpr size_t SZ_W2P   = (size_t)2 * NEXP * CAP * DMODEL * 4;   // 21 MB
constexpr size_t SCRATCH_BYTES = OFF_W2P + SZ_W2P;

__device__ __align__(256) unsigned char g_scratch[SCRATCH_BYTES];

// ---------------------------------------------------------------------------
// helpers
// ---------------------------------------------------------------------------
__device__ __forceinline__ void mma16816(float* c,
                                         uint32_t a0, uint32_t a1, uint32_t a2, uint32_t a3,
                                         uint32_t b0, uint32_t b1) {
    asm volatile(
        "mma.sync.aligned.m16n8k16.row.col.f32.bf16.bf16.f32 "
        "{%0,%1,%2,%3}, {%4,%5,%6,%7}, {%8,%9}, {%0,%1,%2,%3};"
        : "+f"(c[0]), "+f"(c[1]), "+f"(c[2]), "+f"(c[3])
        : "r"(a0), "r"(a1), "r"(a2), "r"(a3), "r"(b0), "r"(b1));
}

__device__ __forceinline__ void ldsm_x4(uint32_t* r, uint32_t saddr) {
    asm volatile("ldmatrix.sync.aligned.m8n8.x4.shared.b16 {%0,%1,%2,%3}, [%4];"
        : "=r"(r[0]), "=r"(r[1]), "=r"(r[2]), "=r"(r[3]) : "r"(saddr));
}
__device__ __forceinline__ void ldsm_x2(uint32_t* r, uint32_t saddr) {
    asm volatile("ldmatrix.sync.aligned.m8n8.x2.shared.b16 {%0,%1}, [%2];"
        : "=r"(r[0]), "=r"(r[1]) : "r"(saddr));
}

__device__ __forceinline__ uint32_t bf162_bits(float l0, float l1) {
    __nv_bfloat162 p = __floats2bfloat162_rn(l0, l1);
    uint32_t u;
    memcpy(&u, &p, 4);
    return u;
}

// ---------------------------------------------------------------------------
// HMMA GEMM (bf16 trunc-split-2, fp32 accumulate), mma.sync + ldmatrix.
//   C[m,n] = sum_k A[m,k]*B[n,k]  (B K-major)   TRB: B global [K,Nd] row-major
//   KSPL: split-K factor; z = batch*KSPL + split; split writes C + split*sPart
//   (epilogue flags must be off for KSPL>1; partials combined by add kernels).
// ---------------------------------------------------------------------------
template<int BM, int BN, bool TRB, bool BIAS, bool RELU, bool RESID,
         bool MASKSCALE, bool CTRIM, int KSPL>
__global__ void __launch_bounds__(256, 1) mma_gemm(
    const float* __restrict__ A, const float* __restrict__ B,
    const float* __restrict__ bias, const float* __restrict__ resid,
    float* __restrict__ C,
    int M, int Nd, int K, int lda, int ldb, int ldc,
    long long sA, long long sB, long long sC, long long sBias, long long sPart)
{
    constexpr int BK = 32;
    constexpr int STR = 80;                 // bytes per smem row (32 bf16 + pad)
    constexpr int WMW = (BM >= 128) ? 2 : 1;
    constexpr int MT  = BM / (WMW * 16);
    constexpr int WNW = 8 / WMW;
    constexpr int WNSZ = BN / WNW;
    constexpr int NT  = WNSZ / 8;
    constexpr int NA4 = BM / 32;
    constexpr int NB4 = BN / 32;
    constexpr int BUFB = (2 * BM + 2 * BN) * STR;

    extern __shared__ unsigned char dsm[];

    const int tid = threadIdx.x;
    const int wid = tid >> 5, lane = tid & 31;
    const int wm = (WMW == 2) ? (wid & 1) : 0;
    const int wn = (WMW == 2) ? (wid >> 1) : wid;
    const int gid = lane >> 2, tig = lane & 3;
    const uint32_t dsm_s = (uint32_t)__cvta_generic_to_shared(dsm);
    const uint32_t laneA = (uint32_t)((lane & 15) * STR + (lane >> 4) * 16);
    const uint32_t laneB = (uint32_t)((lane & 7) * STR + ((lane >> 3) & 1) * 16);

    const int zb  = blockIdx.z / KSPL;
    const int ksp = blockIdx.z % KSPL;
    A += (long long)zb * sA;
    B += (long long)zb * sB;
    C += (long long)zb * sC + (long long)ksp * sPart;
    const float* bptr = nullptr;
    if (BIAS) bptr = bias + (long long)zb * sBias;

    const int m0 = blockIdx.y * BM;
    const int n0 = blockIdx.x * BN;

    if (MASKSCALE) {
        int hardLim = (m0 + BM + 255) & ~255;   // beyond triangular-softmax reads
        if (n0 >= hardLim) return;
        if (n0 > m0 + BM - 1) {   // fully masked tile: fill -inf, skip compute
            for (int i = tid; i < BM * BN / 4; i += 256) {
                int r = i / (BN / 4), c = (i % (BN / 4)) * 4;
                if (m0 + r < M)
                    *(float4*)&C[(long long)(m0 + r) * ldc + n0 + c] =
                        make_float4(-INFINITY, -INFINITY, -INFINITY, -INFINITY);
            }
            return;
        }
    }

    float acc[MT][NT][4];
    #pragma unroll
    for (int i = 0; i < MT; i++)
        #pragma unroll
        for (int j = 0; j < NT; j++)
            #pragma unroll
            for (int l = 0; l < 4; l++) acc[i][j][l] = 0.f;

    float4 aS[NA4], bS[NB4];

    auto ldA = [&](int k0) {
        #pragma unroll
        for (int i = 0; i < NA4; i++) {
            int j = tid + i * 256;
            int r = j >> 3, c = (j & 7) * 4;
            aS[i] = (m0 + r < M) ? *(const float4*)&A[(long long)(m0 + r) * lda + k0 + c]
                                 : make_float4(0.f, 0.f, 0.f, 0.f);
        }
    };
    auto ldB = [&](int k0) {
        if (!TRB) {
            #pragma unroll
            for (int i = 0; i < NB4; i++) {
                int j = tid + i * 256;
                int r = j >> 3, c = (j & 7) * 4;
                bS[i] = (n0 + r < Nd) ? *(const float4*)&B[(long long)(n0 + r) * ldb + k0 + c]
                                      : make_float4(0.f, 0.f, 0.f, 0.f);
            }
        } else {
            #pragma unroll
            for (int i = 0; i < NB4; i++) {
                int j = tid + i * 256;
                int r = j / (BN / 4), c = (j % (BN / 4)) * 4;
                bS[i] = *(const float4*)&B[(long long)(k0 + r) * ldb + n0 + c];
            }
        }
    };
    auto stA = [&](unsigned char* bufb) {
        unsigned char* Ah = bufb;
        unsigned char* Al = bufb + BM * STR;
        #pragma unroll
        for (int i = 0; i < NA4; i++) {
            int j = tid + i * 256;
            int r = j >> 3, c4 = j & 7;
            uint4 u;
            memcpy(&u, &aS[i], 16);
            uint32_t h01 = __byte_perm(u.x, u.y, 0x7632);
            uint32_t h23 = __byte_perm(u.z, u.w, 0x7632);
            float l0 = aS[i].x - __uint_as_float(u.x & 0xffff0000u);
            float l1 = aS[i].y - __uint_as_float(u.y & 0xffff0000u);
            float l2 = aS[i].z - __uint_as_float(u.z & 0xffff0000u);
            float l3 = aS[i].w - __uint_as_float(u.w & 0xffff0000u);
            uint32_t off = (uint32_t)(r * STR + c4 * 8);
            *(uint2*)(Ah + off) = make_uint2(h01, h23);
            *(uint2*)(Al + off) = make_uint2(bf162_bits(l0, l1), bf162_bits(l2, l3));
        }
    };
    auto stB = [&](unsigned char* bufb) {
        unsigned char* Bh = bufb + 2 * BM * STR;
        unsigned char* Bl = bufb + 2 * BM * STR + BN * STR;
        if (!TRB) {
            #pragma unroll
            for (int i = 0; i < NB4; i++) {
                int j = tid + i * 256;
                int r = j >> 3, c4 = j & 7;
                uint4 u;
                memcpy(&u, &bS[i], 16);
                uint32_t h01 = __byte_perm(u.x, u.y, 0x7632);
                uint32_t h23 = __byte_perm(u.z, u.w, 0x7632);
                float l0 = bS[i].x - __uint_as_float(u.x & 0xffff0000u);
                float l1 = bS[i].y - __uint_as_float(u.y & 0xffff0000u);
                float l2 = bS[i].z - __uint_as_float(u.z & 0xffff0000u);
                float l3 = bS[i].w - __uint_as_float(u.w & 0xffff0000u);
                uint32_t off = (uint32_t)(r * STR + c4 * 8);
                *(uint2*)(Bh + off) = make_uint2(h01, h23);
                *(uint2*)(Bl + off) = make_uint2(bf162_bits(l0, l1), bf162_bits(l2, l3));
            }
        } else {
            #pragma unroll
            for (int i = 0; i < NB4; i++) {
                int j = tid + i * 256;
                int r = j / (BN / 4), c4 = j % (BN / 4);
                float v[4] = {bS[i].x, bS[i].y, bS[i].z, bS[i].w};
                #pragma unroll
                for (int q = 0; q < 4; q++) {
                    int n = c4 * 4 + q;
                    uint32_t ub = __float_as_uint(v[q]);
                    unsigned short h = (unsigned short)(ub >> 16);
                    float lof = v[q] - __uint_as_float(ub & 0xffff0000u);
                    unsigned short l = __bfloat16_as_ushort(__float2bfloat16_rn(lof));
                    uint32_t off = (uint32_t)(n * STR + r * 2);
                    *(unsigned short*)(Bh + off) = h;
                    *(unsigned short*)(Bl + off) = l;
                }
            }
        }
    };

    auto compute = [&](uint32_t bufo) {
        const uint32_t AhS = dsm_s + bufo;
        const uint32_t AlS = AhS + BM * STR;
        const uint32_t BhS = dsm_s + bufo + 2 * BM * STR;
        const uint32_t BlS = BhS + BN * STR;
        #pragma unroll
        for (int ks = 0; ks < 2; ks++) {
            const uint32_t kb = (uint32_t)(ks * 32);
            uint32_t a[MT][4], b[NT][2], bl[NT][2];
            #pragma unroll
            for (int ms = 0; ms < MT; ms++)
                ldsm_x4(a[ms], AhS + (uint32_t)((wm * (MT * 16) + ms * 16) * STR) + kb + laneA);
            #pragma unroll
            for (int ns = 0; ns < NT; ns++) {
                uint32_t bo = (uint32_t)((wn * WNSZ + ns * 8) * STR) + kb + laneB;
                ldsm_x2(b[ns],  BhS + bo);
                ldsm_x2(bl[ns], BlS + bo);
            }
            #pragma unroll
            for (int ms = 0; ms < MT; ms++)
                #pragma unroll
                for (int ns = 0; ns < NT; ns++)
                    mma16816(acc[ms][ns], a[ms][0], a[ms][1], a[ms][2], a[ms][3],
                             b[ns][0], b[ns][1]);
            #pragma unroll
            for (int ms = 0; ms < MT; ms++)
                #pragma unroll
                for (int ns = 0; ns < NT; ns++)
                    mma16816(acc[ms][ns], a[ms][0], a[ms][1], a[ms][2], a[ms][3],
                             bl[ns][0], bl[ns][1]);
            #pragma unroll
            for (int ms = 0; ms < MT; ms++)
                ldsm_x4(a[ms], AlS + (uint32_t)((wm * (MT * 16) + ms * 16) * STR) + kb + laneA);
            #pragma unroll
            for (int ms = 0; ms < MT; ms++)
                #pragma unroll
                for (int ns = 0; ns < NT; ns++)
                    mma16816(acc[ms][ns], a[ms][0], a[ms][1], a[ms][2], a[ms][3],
                             b[ns][0], b[ns][1]);
        }
    };

    int nch = K >> 5;
    if (CTRIM) { int lim = (m0 + BM) >> 5; nch = nch < lim ? nch : lim; }
    int kBeg = 0, kEnd = nch;
    if (KSPL > 1) {
        int part = (nch + KSPL - 1) / KSPL;
        kBeg = ksp * part;
        kEnd = kBeg + part < nch ? kBeg + part : nch;
        if (kBeg > nch) kBeg = nch;
    }

    if (kBeg < kEnd) {
        ldA(kBeg << 5); ldB(kBeg << 5);
        stA(dsm); stB(dsm);
        __syncthreads();
        for (int c = kBeg; c < kEnd; c++) {
            if (c + 1 < kEnd) { ldA((c + 1) << 5); ldB((c + 1) << 5); }
            compute((uint32_t)(((c - kBeg) & 1) * BUFB));
            if (c + 1 < kEnd) {
                unsigned char* nb = dsm + (((c + 1 - kBeg) & 1) * BUFB);
                stA(nb); stB(nb);
            }
            __syncthreads();
        }
    }

    // ---- epilogue: direct stores from accumulators
    #pragma unroll
    for (int ms = 0; ms < MT; ms++) {
        #pragma unroll
        for (int ns = 0; ns < NT; ns++) {
            int m = m0 + wm * (MT * 16) + ms * 16 + gid;
            int n = n0 + wn * WNSZ + ns * 8 + tig * 2;
            float* cp = acc[ms][ns];
            #pragma unroll
            for (int half = 0; half < 2; half++) {
                int mm = m + half * 8;
                if (mm >= M) continue;
                float v0 = cp[half * 2 + 0], v1 = cp[half * 2 + 1];
                if (BIAS) { v0 += bptr[n]; v1 += bptr[n + 1]; }
                if (MASKSCALE) {
                    v0 *= 0.125f; v1 *= 0.125f;
                    if (n > mm) v0 = -INFINITY;
                    if (n + 1 > mm) v1 = -INFINITY;
                }
                if (RELU) { v0 = fmaxf(v0, 0.f); v1 = fmaxf(v1, 0.f); }
                if (RESID) {
                    float2 rr = *(const float2*)&resid[(long long)mm * ldc + n];
                    v0 += rr.x; v1 += rr.y;
                }
                *(float2*)&C[(long long)mm * ldc + n] = make_float2(v0, v1);
            }
        }
    }
}

// ---------------------------------------------------------------------------
// Split-K combine kernels
// ---------------------------------------------------------------------------
// PV: ctx[t, ho + h*64 + d] = p0[h][t][d] + p1[h][t][d]
__global__ void __launch_bounds__(256) addpv_k(const float* __restrict__ part,
                                               float* __restrict__ ctxg) {
    int t = blockIdx.x;
    int h = threadIdx.x >> 6, d = threadIdx.x & 63;
    long long o = ((long long)h * NTOK + t) * DHEAD + d;
    float s = part[o] + part[(long long)HGRP * NTOK * DHEAD + o];
    ctxg[(long long)t * DMODEL + h * DHEAD + d] = s;
}

// w2: ye[e][r][d] = p0 + p1 + b2[e][d]   (float4 over 16*160*1024 elems)
__global__ void __launch_bounds__(256) addw2_k(const float* __restrict__ part,
                                               const float* __restrict__ b2,
                                               float* __restrict__ ye) {
    long long i4 = (long long)blockIdx.x * 256 + threadIdx.x;   // float4 index
    constexpr long long TOT4 = (long long)NEXP * CAP * DMODEL / 4;
    if (i4 >= TOT4) return;
    constexpr long long SP4 = (long long)NEXP * CAP * DMODEL / 4;
    float4 a = ((const float4*)part)[i4];
    float4 b = ((const float4*)part)[SP4 + i4];
    long long e = i4 / ((long long)CAP * DMODEL / 4);
    long long col4 = i4 % ((long long)DMODEL / 4);
    float4 bb = ((const float4*)(b2 + e * DMODEL))[col4];
    ((float4*)ye)[i4] = make_float4(a.x + b.x + bb.x, a.y + b.y + bb.y,
                                    a.z + b.z + bb.z, a.w + b.w + bb.w);
}

// ---------------------------------------------------------------------------
// Pack wk|wq|wv and bk|bq|bv into contiguous scratch for one z=3 launch
// ---------------------------------------------------------------------------
__global__ void __launch_bounds__(256) pack3_k(
    const float* __restrict__ a0, const float* __restrict__ a1, const float* __restrict__ a2,
    const float* __restrict__ b0, const float* __restrict__ b1, const float* __restrict__ b2,
    float* __restrict__ w, float* __restrict__ b)
{
    constexpr int N4 = DMODEL * DMODEL / 4;
    int idx = blockIdx.x * 256 + threadIdx.x;
    if (idx < 3 * N4) {
        const float* src = (idx < N4) ? a0 : (idx < 2 * N4) ? a1 : a2;
        int loc = idx - (idx < N4 ? 0 : (idx < 2 * N4 ? N4 : 2 * N4));
        ((float4*)w)[idx] = ((const float4*)src)[loc];
    }
    if (idx < 3 * DMODEL / 4) {
        constexpr int B4 = DMODEL / 4;
        const float* src = (idx < B4) ? b0 : (idx < 2 * B4) ? b1 : b2;
        int loc = idx - (idx < B4 ? 0 : (idx < 2 * B4 ? B4 : 2 * B4));
        ((float4*)b)[idx] = ((const float4*)src)[loc];
    }
}

// ---------------------------------------------------------------------------
// Block reductions + glue kernels
// ---------------------------------------------------------------------------
__device__ __forceinline__ float blockReduceSum(float val, float* red) {
    int lane = threadIdx.x & 31, wid = threadIdx.x >> 5;
    #pragma unroll
    for (int o = 16; o; o >>= 1) val += __shfl_down_sync(0xffffffffu, val, o);
    __syncthreads();
    if (lane == 0) red[wid] = val;
    __syncthreads();
    if (threadIdx.x < 32) {
        val = (lane < 8) ? red[lane] : 0.f;
        #pragma unroll
        for (int o = 4; o; o >>= 1) val += __shfl_down_sync(0xffffffffu, val, o);
        if (lane == 0) red[0] = val;
    }
    __syncthreads();
    return red[0];
}
__device__ __forceinline__ float blockReduceMax(float val, float* red) {
    int lane = threadIdx.x & 31, wid = threadIdx.x >> 5;
    #pragma unroll
    for (int o = 16; o; o >>= 1) val = fmaxf(val, __shfl_down_sync(0xffffffffu, val, o));
    __syncthreads();
    if (lane == 0) red[wid] = val;
    __syncthreads();
    if (threadIdx.x < 32) {
        val = (lane < 8) ? red[lane] : -INFINITY;
        #pragma unroll
        for (int o = 4; o; o >>= 1) val = fmaxf(val, __shfl_down_sync(0xffffffffu, val, o));
        if (lane == 0) red[0] = val;
    }
    __syncthreads();
    return red[0];
}

__global__ void __launch_bounds__(256) ln_k(const float* __restrict__ x,
                                            const float* __restrict__ w,
                                            const float* __restrict__ b,
                                            float* __restrict__ out) {
    __shared__ float red[8];
    int row = blockIdx.x, tid = threadIdx.x;
    const float* xr = x + (size_t)row * DMODEL;
    float v[4];
    float s = 0.f;
    #pragma unroll
    for (int i = 0; i < 4; i++) { v[i] = xr[tid + i * 256]; s += v[i]; }
    s = blockReduceSum(s, red);
    float mu = s * (1.f / DMODEL);
    float s2 = 0.f;
    #pragma unroll
    for (int i = 0; i < 4; i++) { float d = v[i] - mu; s2 += d * d; }
    s2 = blockReduceSum(s2, red);
    float rstd = rsqrtf(s2 * (1.f / DMODEL) + 1e-5f);
    float* orow = out + (size_t)row * DMODEL;
    #pragma unroll
    for (int i = 0; i < 4; i++) {
        int c = tid + i * 256;
        orow[c] = (v[i] - mu) * rstd * w[c] + b[c];
    }
}

// Triangular softmax: row r only processes ceil((r+1)/256)*256 columns.
__global__ void __launch_bounds__(256) softmax_k(float* __restrict__ S) {
    __shared__ float red[8];
    int r = blockIdx.x & (NTOK - 1);
    float* row = S + (long long)blockIdx.x * NTOK;
    int tid = threadIdx.x;
    int nit = (r >> 8) + 1;
    float v[8];
    float mx = -INFINITY;
    #pragma unroll
    for (int i = 0; i < 8; i++) {
        if (i < nit) { v[i] = row[tid + i * 256]; mx = fmaxf(mx, v[i]); }
    }
    mx = blockReduceMax(mx, red);
    float s = 0.f;
    #pragma unroll
    for (int i = 0; i < 8; i++) {
        if (i < nit) { v[i] = expf(v[i] - mx); s += v[i]; }
    }
    s = blockReduceSum(s, red);
    float inv = 1.f / s;
    #pragma unroll
    for (int i = 0; i < 8; i++) {
        if (i < nit) row[tid + i * 256] = v[i] * inv;
    }
}

__global__ void __launch_bounds__(512) router_k(const float* __restrict__ h,
                                                const float* __restrict__ rw,
                                                const float* __restrict__ rb,
                                                int* __restrict__ routes,
                                                float* __restrict__ pmax) {
    __shared__ float lg[NEXP];
    int t = blockIdx.x;
    int wid = threadIdx.x >> 5, lane = threadIdx.x & 31;
    const float* hr = h + (size_t)t * DMODEL;
    const float* wr = rw + (size_t)wid * DMODEL;
    float s = 0.f;
    for (int k = lane; k < DMODEL; k += 32) s += hr[k] * wr[k];
    #pragma unroll
    for (int o = 16; o; o >>= 1) s += __shfl_down_sync(0xffffffffu, s, o);
    if (lane == 0) lg[wid] = s + rb[wid];
    __syncthreads();
    if (threadIdx.x == 0) {
        float mx = lg[0]; int arg = 0;
        #pragma unroll
        for (int e = 1; e < NEXP; e++)
            if (lg[e] > mx) { mx = lg[e]; arg = e; }
        float sum = 0.f;
        #pragma unroll
        for (int e = 0; e < NEXP; e++) sum += expf(lg[e] - mx);
        routes[t] = arg;
        pmax[t] = 1.f / sum;
    }
}

__global__ void __launch_bounds__(512) slot_k(const int* __restrict__ routes,
                                              int* __restrict__ slot,
                                              int* __restrict__ keep) {
    __shared__ int sr[NTOK];
    int tid = threadIdx.x;
    for (int i = tid; i < NTOK; i += 512) sr[i] = routes[i];
    __syncthreads();
    int wid = tid >> 5, lane = tid & 31;
    int pos = 0;
    unsigned lmask = (1u << lane) - 1u;
    for (int base = 0; base < NTOK; base += 32) {
        int r = sr[base + lane];
        unsigned m = __ballot_sync(0xffffffffu, r == wid);
        if (r == wid) {
            int p = pos + __popc(m & lmask);
            int kp = (p < CAP) ? 1 : 0;
            keep[base + lane] = kp;
            slot[base + lane] = kp ? (wid * CAP + p) : (NEXP * CAP);
        }
        pos += __popc(m);
    }
}

__global__ void __launch_bounds__(256) gather_k(const float* __restrict__ h,
                                                const int* __restrict__ slot,
                                                const int* __restrict__ keep,
                                                float* __restrict__ buf) {
    int t = blockIdx.x;
    if (!keep[t]) return;
    int s = slot[t];
    const float4* src = (const float4*)(h + (size_t)t * DMODEL);
    float4* dst = (float4*)(buf + (size_t)s * DMODEL);
    dst[threadIdx.x] = src[threadIdx.x];
}

__global__ void __launch_bounds__(256) final_k(const float* __restrict__ x1,
                                               const float* __restrict__ h2,
                                               const float* __restrict__ ye,
                                               const int* __restrict__ slot,
                                               const int* __restrict__ keep,
                                               const float* __restrict__ pmax,
                                               float* __restrict__ out) {
    int t = blockIdx.x;
    float p = pmax[t];
    const float4* ysrc = keep[t]
        ? (const float4*)(ye + (size_t)slot[t] * DMODEL)
        : (const float4*)(h2 + (size_t)t * DMODEL);
    const float4* xs = (const float4*)(x1 + (size_t)t * DMODEL);
    float4 a = xs[threadIdx.x];
    float4 y = ysrc[threadIdx.x];
    float4 o = make_float4(a.x + y.x * p, a.y + y.y * p, a.z + y.z * p, a.w + y.w * p);
    ((float4*)out)[(size_t)t * (DMODEL / 4) + threadIdx.x] = o;
}

// ---------------------------------------------------------------------------
// Launch
// ---------------------------------------------------------------------------
extern "C" void kernel_launch(void* const* d_in, const int* in_sizes, int n_in,
                              void* d_out, int out_size) {
    const float* x    = (const float*)d_in[0];
    const float* wk   = (const float*)d_in[1];
    const float* bk   = (const float*)d_in[2];
    const float* wq   = (const float*)d_in[3];
    const float* bq   = (const float*)d_in[4];
    const float* wv   = (const float*)d_in[5];
    const float* bv   = (const float*)d_in[6];
    const float* ipw  = (const float*)d_in[7];
    const float* ipb  = (const float*)d_in[8];
    const float* opw  = (const float*)d_in[9];
    const float* opb  = (const float*)d_in[10];
    const float* ln1w = (const float*)d_in[11];
    const float* ln1b = (const float*)d_in[12];
    const float* ln2w = (const float*)d_in[13];
    const float* ln2b = (const float*)d_in[14];
    const float* rw   = (const float*)d_in[15];
    const float* rb   = (const float*)d_in[16];
    const float* w1   = (const float*)d_in[17];
    const float* b1   = (const float*)d_in[18];
    const float* w2   = (const float*)d_in[19];
    const float* b2   = (const float*)d_in[20];
    float* out = (float*)d_out;

    void* sp = nullptr;
    cudaGetSymbolAddress(&sp, g_scratch);
    char* base = (char*)sp;
    float* hln    = (float*)(base + OFF_A);
    float* ctx    = (float*)(base + OFF_A);
    float* qin    = (float*)(base + OFF_B);
    float* x1     = (float*)(base + OFF_B);
    float* h2     = (float*)(base + OFF_C);
    float* pvp    = (float*)(base + OFF_D);    // PV split partials (4MB)
    float* q      = (float*)(base + OFF_E);
    float* ye     = (float*)(base + OFF_E);
    float* k      = (float*)(base + OFF_F);
    float* v      = (float*)(base + OFF_G);
    float* buf    = (float*)(base + OFF_G);
    float* sc     = (float*)(base + OFF_SC);
    float* hexp   = (float*)(base + OFF_HEXP);
    float* w2p    = (float*)(base + OFF_W2P);
    float* pakw   = (float*)(base + OFF_PAKW);
    float* pakb   = (float*)(base + OFF_PAKB);
    int*   routes = (int*)(base + OFF_ROUTES);
    int*   slot   = (int*)(base + OFF_SLOT);
    int*   keep   = (int*)(base + OFF_KEEP);
    float* pmax   = (float*)(base + OFF_PMAX);

    // instantiations + dynamic smem opt-in (round-11 configs + split-K variants)
    auto GP   = mma_gemm<128, 128, false, true,  false, false, false, false, 1>;  // proj
    auto GPR  = mma_gemm<128, 128, false, true,  false, true,  false, false, 1>;  // out-proj+resid
    auto GQK  = mma_gemm<128, 128, false, false, false, false, true,  false, 1>;  // QK^T masked
    auto GPVS = mma_gemm<64,  64,  true,  false, false, false, false, true,  2>;  // P@V split-K
    auto GW1  = mma_gemm<160, 128, false, true,  true,  false, false, false, 1>;  // w1+relu
    auto GW2S = mma_gemm<160, 128, false, false, false, false, false, false, 2>;  // w2 split-K
    constexpr int SM128 = 2 * (2 * 128 + 2 * 128) * 80;   // 81920
    constexpr int SM64  = 2 * (2 * 64  + 2 * 64)  * 80;   // 40960
    constexpr int SM160 = 2 * (2 * 160 + 2 * 128) * 80;   // 92160
    cudaFuncSetAttribute(GP,   cudaFuncAttributeMaxDynamicSharedMemorySize, SM128);
    cudaFuncSetAttribute(GPR,  cudaFuncAttributeMaxDynamicSharedMemorySize, SM128);
    cudaFuncSetAttribute(GQK,  cudaFuncAttributeMaxDynamicSharedMemorySize, SM128);
    cudaFuncSetAttribute(GPVS, cudaFuncAttributeMaxDynamicSharedMemorySize, SM64);
    cudaFuncSetAttribute(GW1,  cudaFuncAttributeMaxDynamicSharedMemorySize, SM160);
    cudaFuncSetAttribute(GW2S, cudaFuncAttributeMaxDynamicSharedMemorySize, SM160);

    // ---- LN1 + weight packing (independent)
    ln_k<<<NTOK, 256>>>(x, ln1w, ln1b, hln);
    pack3_k<<<(3 * DMODEL * DMODEL / 4 + 255) / 256, 256>>>(
        wk, wq, wv, bk, bq, bv, pakw, pakb);

    // ---- first projections: ONE z=3 batched launch
    //      (swapped K/Q per reference: z order wk,wq,wv -> qin,kin,vin)
    dim3 gD3(DMODEL / 128, NTOK / 128, 3);
    GP<<<gD3, 256, SM128>>>(hln, pakw, pakb, nullptr, qin,
        NTOK, DMODEL, DMODEL, DMODEL, DMODEL, DMODEL,
        0, (long long)DMODEL * DMODEL, (long long)NTOK * DMODEL, DMODEL, 0);

    // ---- in_proj splits: one batched launch
    GP<<<gD3, 256, SM128>>>(qin, ipw, ipb, nullptr, q,
        NTOK, DMODEL, DMODEL, DMODEL, DMODEL, DMODEL,
        (long long)NTOK * DMODEL, (long long)DMODEL * DMODEL,
        (long long)NTOK * DMODEL, DMODEL, 0);

    // ---- attention: groups of HGRP heads, z-batched; PV split-K x2
    for (int g = 0; g < NHEAD / HGRP; g++) {
        const int ho = g * HGRP * DHEAD;
        dim3 gS(NTOK / 128, NTOK / 128, HGRP);
        GQK<<<gS, 256, SM128>>>(q + ho, k + ho, nullptr, nullptr, sc,
            NTOK, NTOK, DHEAD, DMODEL, DMODEL, NTOK,
            DHEAD, DHEAD, (long long)NTOK * NTOK, 0, 0);
        softmax_k<<<HGRP * NTOK, 256>>>(sc);
        dim3 gV(1, NTOK / 64, HGRP * 2);
        GPVS<<<gV, 256, SM64>>>(sc, v + ho, nullptr, nullptr, pvp,
            NTOK, DHEAD, NTOK, NTOK, DMODEL, DHEAD,
            (long long)NTOK * NTOK, DHEAD, (long long)NTOK * DHEAD, 0,
            (long long)HGRP * NTOK * DHEAD);
        addpv_k<<<NTOK, 256>>>(pvp, ctx + ho);
    }

    // ---- x1 = x + ctx @ opw^T + opb
    dim3 gD(DMODEL / 128, NTOK / 128, 1);
    GPR<<<gD, 256, SM128>>>(ctx, opw, opb, x, x1,
        NTOK, DMODEL, DMODEL, DMODEL, DMODEL, DMODEL, 0, 0, 0, 0, 0);

    // ---- LN2
    ln_k<<<NTOK, 256>>>(x1, ln2w, ln2b, h2);

    // ---- router + routing + gather
    router_k<<<NTOK, 512>>>(h2, rw, rb, routes, pmax);
    slot_k<<<1, 512>>>(routes, slot, keep);
    gather_k<<<NTOK, 256>>>(h2, slot, keep, buf);

    // ---- expert FFN layer 1 (relu): single BM=160 launch
    dim3 g1(FEXP / 128, 1, NEXP);
    GW1<<<g1, 256, SM160>>>(buf, w1, b1, nullptr, hexp,
        CAP, FEXP, DMODEL, DMODEL, DMODEL, FEXP,
        (long long)CAP * DMODEL, (long long)FEXP * DMODEL,
        (long long)CAP * FEXP, FEXP, 0);

    // ---- expert FFN layer 2: split-K x2 (256 CTAs) + bias-fused combine
    dim3 g2(DMODEL / 128, 1, NEXP * 2);
    GW2S<<<g2, 256, SM160>>>(hexp, w2, nullptr, nullptr, w2p,
        CAP, DMODEL, FEXP, FEXP, FEXP, DMODEL,
        (long long)CAP * FEXP, (long long)DMODEL * FEXP,
        (long long)CAP * DMODEL, 0,
        (long long)NEXP * CAP * DMODEL);
    addw2_k<<<(int)(((long long)NEXP * CAP * DMODEL / 4 + 255) / 256), 256>>>(
        w2p, b2, ye);

    // ---- final combine
    final_k<<<NTOK, 256>>>(x1, h2, ye, slot, keep, pmax, out);
}

// round 15
// speedup vs baseline: 1.0542x; 1.0050x over previous
#include <cuda_runtime.h>
#include <cuda_bf16.h>
#include <math.h>
#include <stdint.h>
#include <string.h>

#define NTOK   2048
#define DMODEL 1024
#define NHEAD  16
#define DHEAD  64
#define FEXP   4096
#define NEXP   16
#define CAP    160      // int(1.25 * 2048 / 16)
#define HGRP   4        // heads per attention group

// ---------------------------------------------------------------------------
// Scratch (single __device__ bss array; aliased). ~123 MB total.
// ---------------------------------------------------------------------------
constexpr size_t SZ_ND = (size_t)NTOK * DMODEL * 4;            // 8 MB
constexpr size_t OFF_A    = 0;               // hln -> ctx
constexpr size_t OFF_B    = 1 * SZ_ND;       // qin -> x1
constexpr size_t OFF_C    = 2 * SZ_ND;       // kin -> h2
constexpr size_t OFF_D    = 3 * SZ_ND;       // vin
constexpr size_t OFF_E    = 4 * SZ_ND;       // q -> ye
constexpr size_t OFF_F    = 5 * SZ_ND;       // k
constexpr size_t OFF_G    = 6 * SZ_ND;       // v -> buf (spills 2.5MB into SC)
constexpr size_t OFF_SC   = 7 * SZ_ND;       // scores: HGRP x 16MB = 64MiB
constexpr size_t SZ_SC    = (size_t)HGRP * NTOK * NTOK * 4;
constexpr size_t OFF_HEXP = OFF_SC + (size_t)(4 << 20);        // clear of buf spill
constexpr size_t OFF_PAKW = OFF_HEXP;                          // 12 MB (pack region)
constexpr size_t OFF_PAKB = OFF_PAKW + (size_t)3 * DMODEL * DMODEL * 4;
constexpr size_t OFF_ROUTES = OFF_SC + SZ_SC;
constexpr size_t OFF_SLOT   = OFF_ROUTES + (size_t)NTOK * 4;
constexpr size_t OFF_KEEP   = OFF_SLOT   + (size_t)NTOK * 4;
constexpr size_t OFF_PMAX   = OFF_KEEP   + (size_t)NTOK * 4;
constexpr size_t SCRATCH_BYTES = OFF_PMAX + (size_t)NTOK * 4;

__device__ __align__(256) unsigned char g_scratch[SCRATCH_BYTES];

// ---------------------------------------------------------------------------
// helpers
// ---------------------------------------------------------------------------
__device__ __forceinline__ void mma16816(float* c,
                                         uint32_t a0, uint32_t a1, uint32_t a2, uint32_t a3,
                                         uint32_t b0, uint32_t b1) {
    asm volatile(
        "mma.sync.aligned.m16n8k16.row.col.f32.bf16.bf16.f32 "
        "{%0,%1,%2,%3}, {%4,%5,%6,%7}, {%8,%9}, {%0,%1,%2,%3};"
        : "+f"(c[0]), "+f"(c[1]), "+f"(c[2]), "+f"(c[3])
        : "r"(a0), "r"(a1), "r"(a2), "r"(a3), "r"(b0), "r"(b1));
}

__device__ __forceinline__ void ldsm_x4(uint32_t* r, uint32_t saddr) {
    asm volatile("ldmatrix.sync.aligned.m8n8.x4.shared.b16 {%0,%1,%2,%3}, [%4];"
        : "=r"(r[0]), "=r"(r[1]), "=r"(r[2]), "=r"(r[3]) : "r"(saddr));
}
__device__ __forceinline__ void ldsm_x2(uint32_t* r, uint32_t saddr) {
    asm volatile("ldmatrix.sync.aligned.m8n8.x2.shared.b16 {%0,%1}, [%2];"
        : "=r"(r[0]), "=r"(r[1]) : "r"(saddr));
}

__device__ __forceinline__ uint32_t bf162_bits(float l0, float l1) {
    __nv_bfloat162 p = __floats2bfloat162_rn(l0, l1);
    uint32_t u;
    memcpy(&u, &p, 4);
    return u;
}

// ---------------------------------------------------------------------------
// HMMA GEMM (bf16 trunc-split-2, fp32 accumulate), mma.sync + ldmatrix.
//   C[m,n] = sum_k A[m,k]*B[n,k]  (B K-major)   TRB: B global [K,Nd] row-major
//   CH: k-chunk per smem stage (32 or 64). BM in {160,128,64}; BN in {64,128}.
//   256 thr = 8 warps, 1 CTA/SM, double-buffered smem, 1 sync per chunk.
// ---------------------------------------------------------------------------
template<int BM, int BN, int CH, bool TRB, bool BIAS, bool RELU, bool RESID,
         bool MASKSCALE, bool CTRIM>
__global__ void __launch_bounds__(256, 1) mma_gemm(
    const float* __restrict__ A, const float* __restrict__ B,
    const float* __restrict__ bias, const float* __restrict__ resid,
    float* __restrict__ C,
    int M, int Nd, int K, int lda, int ldb, int ldc,
    long long sA, long long sB, long long sC, long long sBias)
{
    constexpr int STR = (CH == 64) ? 144 : 80;   // bytes/row (CH bf16 + 16B pad)
    constexpr int NKS = CH / 16;                 // mma k-steps per chunk
    constexpr int C4  = CH / 4;                  // float4s per row
    constexpr int WMW = (BM >= 128) ? 2 : 1;
    constexpr int MT  = BM / (WMW * 16);
    constexpr int WNW = 8 / WMW;
    constexpr int WNSZ = BN / WNW;
    constexpr int NT  = WNSZ / 8;
    constexpr int NA4 = BM * CH / 1024;          // float4 loads/thread for A
    constexpr int NB4 = BN * CH / 1024;
    constexpr int BUFB = (2 * BM + 2 * BN) * STR;

    extern __shared__ unsigned char dsm[];

    const int tid = threadIdx.x;
    const int wid = tid >> 5, lane = tid & 31;
    const int wm = (WMW == 2) ? (wid & 1) : 0;
    const int wn = (WMW == 2) ? (wid >> 1) : wid;
    const int gid = lane >> 2, tig = lane & 3;
    const uint32_t dsm_s = (uint32_t)__cvta_generic_to_shared(dsm);
    const uint32_t laneA = (uint32_t)((lane & 15) * STR + (lane >> 4) * 16);
    const uint32_t laneB = (uint32_t)((lane & 7) * STR + ((lane >> 3) & 1) * 16);

    A += (long long)blockIdx.z * sA;
    B += (long long)blockIdx.z * sB;
    C += (long long)blockIdx.z * sC;
    const float* bptr = nullptr;
    if (BIAS) bptr = bias + (long long)blockIdx.z * sBias;

    const int m0 = blockIdx.y * BM;
    const int n0 = blockIdx.x * BN;

    if (MASKSCALE) {
        int hardLim = (m0 + BM + 255) & ~255;   // beyond triangular-softmax reads
        if (n0 >= hardLim) return;
        if (n0 > m0 + BM - 1) {   // fully masked tile: fill -inf, skip compute
            for (int i = tid; i < BM * BN / 4; i += 256) {
                int r = i / (BN / 4), c = (i % (BN / 4)) * 4;
                if (m0 + r < M)
                    *(float4*)&C[(long long)(m0 + r) * ldc + n0 + c] =
                        make_float4(-INFINITY, -INFINITY, -INFINITY, -INFINITY);
            }
            return;
        }
    }

    float acc[MT][NT][4];
    #pragma unroll
    for (int i = 0; i < MT; i++)
        #pragma unroll
        for (int j = 0; j < NT; j++)
            #pragma unroll
            for (int l = 0; l < 4; l++) acc[i][j][l] = 0.f;

    float4 aS[NA4], bS[NB4];

    auto ldA = [&](int k0) {
        #pragma unroll
        for (int i = 0; i < NA4; i++) {
            int j = tid + i * 256;
            int r = j / C4, c = (j % C4) * 4;
            aS[i] = (m0 + r < M) ? *(const float4*)&A[(long long)(m0 + r) * lda + k0 + c]
                                 : make_float4(0.f, 0.f, 0.f, 0.f);
        }
    };
    auto ldB = [&](int k0) {
        if (!TRB) {
            #pragma unroll
            for (int i = 0; i < NB4; i++) {
                int j = tid + i * 256;
                int r = j / C4, c = (j % C4) * 4;
                bS[i] = (n0 + r < Nd) ? *(const float4*)&B[(long long)(n0 + r) * ldb + k0 + c]
                                      : make_float4(0.f, 0.f, 0.f, 0.f);
            }
        } else {
            #pragma unroll
            for (int i = 0; i < NB4; i++) {
                int j = tid + i * 256;
                int r = j / (BN / 4), c = (j % (BN / 4)) * 4;
                bS[i] = *(const float4*)&B[(long long)(k0 + r) * ldb + n0 + c];
            }
        }
    };
    auto stA = [&](unsigned char* bufb) {
        unsigned char* Ah = bufb;
        unsigned char* Al = bufb + BM * STR;
        #pragma unroll
        for (int i = 0; i < NA4; i++) {
            int j = tid + i * 256;
            int r = j / C4, c4 = j % C4;
            uint4 u;
            memcpy(&u, &aS[i], 16);
            uint32_t h01 = __byte_perm(u.x, u.y, 0x7632);
            uint32_t h23 = __byte_perm(u.z, u.w, 0x7632);
            float l0 = aS[i].x - __uint_as_float(u.x & 0xffff0000u);
            float l1 = aS[i].y - __uint_as_float(u.y & 0xffff0000u);
            float l2 = aS[i].z - __uint_as_float(u.z & 0xffff0000u);
            float l3 = aS[i].w - __uint_as_float(u.w & 0xffff0000u);
            uint32_t off = (uint32_t)(r * STR + c4 * 8);
            *(uint2*)(Ah + off) = make_uint2(h01, h23);
            *(uint2*)(Al + off) = make_uint2(bf162_bits(l0, l1), bf162_bits(l2, l3));
        }
    };
    auto stB = [&](unsigned char* bufb) {
        unsigned char* Bh = bufb + 2 * BM * STR;
        unsigned char* Bl = bufb + 2 * BM * STR + BN * STR;
        if (!TRB) {
            #pragma unroll
            for (int i = 0; i < NB4; i++) {
                int j = tid + i * 256;
                int r = j / C4, c4 = j % C4;
                uint4 u;
                memcpy(&u, &bS[i], 16);
                uint32_t h01 = __byte_perm(u.x, u.y, 0x7632);
                uint32_t h23 = __byte_perm(u.z, u.w, 0x7632);
                float l0 = bS[i].x - __uint_as_float(u.x & 0xffff0000u);
                float l1 = bS[i].y - __uint_as_float(u.y & 0xffff0000u);
                float l2 = bS[i].z - __uint_as_float(u.z & 0xffff0000u);
                float l3 = bS[i].w - __uint_as_float(u.w & 0xffff0000u);
                uint32_t off = (uint32_t)(r * STR + c4 * 8);
                *(uint2*)(Bh + off) = make_uint2(h01, h23);
                *(uint2*)(Bl + off) = make_uint2(bf162_bits(l0, l1), bf162_bits(l2, l3));
            }
        } else {
            #pragma unroll
            for (int i = 0; i < NB4; i++) {
                int j = tid + i * 256;
                int r = j / (BN / 4), c4 = j % (BN / 4);
                float v[4] = {bS[i].x, bS[i].y, bS[i].z, bS[i].w};
                #pragma unroll
                for (int q = 0; q < 4; q++) {
                    int n = c4 * 4 + q;
                    uint32_t ub = __float_as_uint(v[q]);
                    unsigned short h = (unsigned short)(ub >> 16);
                    float lof = v[q] - __uint_as_float(ub & 0xffff0000u);
                    unsigned short l = __bfloat16_as_ushort(__float2bfloat16_rn(lof));
                    uint32_t off = (uint32_t)(n * STR + r * 2);
                    *(unsigned short*)(Bh + off) = h;
                    *(unsigned short*)(Bl + off) = l;
                }
            }
        }
    };

    auto compute = [&](uint32_t bufo) {
        const uint32_t AhS = dsm_s + bufo;
        const uint32_t AlS = AhS + BM * STR;
        const uint32_t BhS = dsm_s + bufo + 2 * BM * STR;
        const uint32_t BlS = BhS + BN * STR;
        #pragma unroll
        for (int ks = 0; ks < NKS; ks++) {
            const uint32_t kb = (uint32_t)(ks * 32);
            uint32_t a[MT][4], b[NT][2], bl[NT][2];
            #pragma unroll
            for (int ms = 0; ms < MT; ms++)
                ldsm_x4(a[ms], AhS + (uint32_t)((wm * (MT * 16) + ms * 16) * STR) + kb + laneA);
            #pragma unroll
            for (int ns = 0; ns < NT; ns++) {
                uint32_t bo = (uint32_t)((wn * WNSZ + ns * 8) * STR) + kb + laneB;
                ldsm_x2(b[ns],  BhS + bo);
                ldsm_x2(bl[ns], BlS + bo);
            }
            #pragma unroll
            for (int ms = 0; ms < MT; ms++)
                #pragma unroll
                for (int ns = 0; ns < NT; ns++)
                    mma16816(acc[ms][ns], a[ms][0], a[ms][1], a[ms][2], a[ms][3],
                             b[ns][0], b[ns][1]);
            #pragma unroll
            for (int ms = 0; ms < MT; ms++)
                #pragma unroll
                for (int ns = 0; ns < NT; ns++)
                    mma16816(acc[ms][ns], a[ms][0], a[ms][1], a[ms][2], a[ms][3],
                             bl[ns][0], bl[ns][1]);
            #pragma unroll
            for (int ms = 0; ms < MT; ms++)
                ldsm_x4(a[ms], AlS + (uint32_t)((wm * (MT * 16) + ms * 16) * STR) + kb + laneA);
            #pragma unroll
            for (int ms = 0; ms < MT; ms++)
                #pragma unroll
                for (int ns = 0; ns < NT; ns++)
                    mma16816(acc[ms][ns], a[ms][0], a[ms][1], a[ms][2], a[ms][3],
                             b[ns][0], b[ns][1]);
        }
    };

    int nch = K / CH;
    if (CTRIM) { int lim = (m0 + BM) / CH; nch = nch < lim ? nch : lim; }

    ldA(0); ldB(0);
    stA(dsm); stB(dsm);
    __syncthreads();
    for (int c = 0; c < nch; c++) {
        if (c + 1 < nch) { ldA((c + 1) * CH); ldB((c + 1) * CH); }
        compute((uint32_t)((c & 1) * BUFB));
        if (c + 1 < nch) {
            unsigned char* nb = dsm + ((c + 1) & 1) * BUFB;
            stA(nb); stB(nb);
        }
        __syncthreads();
    }

    // ---- epilogue: direct stores from accumulators
    #pragma unroll
    for (int ms = 0; ms < MT; ms++) {
        #pragma unroll
        for (int ns = 0; ns < NT; ns++) {
            int m = m0 + wm * (MT * 16) + ms * 16 + gid;
            int n = n0 + wn * WNSZ + ns * 8 + tig * 2;
            float* cp = acc[ms][ns];
            #pragma unroll
            for (int half = 0; half < 2; half++) {
                int mm = m + half * 8;
                if (mm >= M) continue;
                float v0 = cp[half * 2 + 0], v1 = cp[half * 2 + 1];
                if (BIAS) { v0 += bptr[n]; v1 += bptr[n + 1]; }
                if (MASKSCALE) {
                    v0 *= 0.125f; v1 *= 0.125f;
                    if (n > mm) v0 = -INFINITY;
                    if (n + 1 > mm) v1 = -INFINITY;
                }
                if (RELU) { v0 = fmaxf(v0, 0.f); v1 = fmaxf(v1, 0.f); }
                if (RESID) {
                    float2 rr = *(const float2*)&resid[(long long)mm * ldc + n];
                    v0 += rr.x; v1 += rr.y;
                }
                *(float2*)&C[(long long)mm * ldc + n] = make_float2(v0, v1);
            }
        }
    }
}

// ---------------------------------------------------------------------------
// Pack wk|wq|wv and bk|bq|bv into contiguous scratch for one z=3 launch
// ---------------------------------------------------------------------------
__global__ void __launch_bounds__(256) pack3_k(
    const float* __restrict__ a0, const float* __restrict__ a1, const float* __restrict__ a2,
    const float* __restrict__ b0, const float* __restrict__ b1, const float* __restrict__ b2,
    float* __restrict__ w, float* __restrict__ b)
{
    constexpr int N4 = DMODEL * DMODEL / 4;
    int idx = blockIdx.x * 256 + threadIdx.x;
    if (idx < 3 * N4) {
        const float* src = (idx < N4) ? a0 : (idx < 2 * N4) ? a1 : a2;
        int loc = idx - (idx < N4 ? 0 : (idx < 2 * N4 ? N4 : 2 * N4));
        ((float4*)w)[idx] = ((const float4*)src)[loc];
    }
    if (idx < 3 * DMODEL / 4) {
        constexpr int B4 = DMODEL / 4;
        const float* src = (idx < B4) ? b0 : (idx < 2 * B4) ? b1 : b2;
        int loc = idx - (idx < B4 ? 0 : (idx < 2 * B4 ? B4 : 2 * B4));
        ((float4*)b)[idx] = ((const float4*)src)[loc];
    }
}

// ---------------------------------------------------------------------------
// Block reductions + glue kernels
// ---------------------------------------------------------------------------
__device__ __forceinline__ float blockReduceSum(float val, float* red) {
    int lane = threadIdx.x & 31, wid = threadIdx.x >> 5;
    #pragma unroll
    for (int o = 16; o; o >>= 1) val += __shfl_down_sync(0xffffffffu, val, o);
    __syncthreads();
    if (lane == 0) red[wid] = val;
    __syncthreads();
    if (threadIdx.x < 32) {
        val = (lane < 8) ? red[lane] : 0.f;
        #pragma unroll
        for (int o = 4; o; o >>= 1) val += __shfl_down_sync(0xffffffffu, val, o);
        if (lane == 0) red[0] = val;
    }
    __syncthreads();
    return red[0];
}
__device__ __forceinline__ float blockReduceMax(float val, float* red) {
    int lane = threadIdx.x & 31, wid = threadIdx.x >> 5;
    #pragma unroll
    for (int o = 16; o; o >>= 1) val = fmaxf(val, __shfl_down_sync(0xffffffffu, val, o));
    __syncthreads();
    if (lane == 0) red[wid] = val;
    __syncthreads();
    if (threadIdx.x < 32) {
        val = (lane < 8) ? red[lane] : -INFINITY;
        #pragma unroll
        for (int o = 4; o; o >>= 1) val = fmaxf(val, __shfl_down_sync(0xffffffffu, val, o));
        if (lane == 0) red[0] = val;
    }
    __syncthreads();
    return red[0];
}

__global__ void __launch_bounds__(256) ln_k(const float* __restrict__ x,
                                            const float* __restrict__ w,
                                            const float* __restrict__ b,
                                            float* __restrict__ out) {
    __shared__ float red[8];
    int row = blockIdx.x, tid = threadIdx.x;
    const float* xr = x + (size_t)row * DMODEL;
    float v[4];
    float s = 0.f;
    #pragma unroll
    for (int i = 0; i < 4; i++) { v[i] = xr[tid + i * 256]; s += v[i]; }
    s = blockReduceSum(s, red);
    float mu = s * (1.f / DMODEL);
    float s2 = 0.f;
    #pragma unroll
    for (int i = 0; i < 4; i++) { float d = v[i] - mu; s2 += d * d; }
    s2 = blockReduceSum(s2, red);
    float rstd = rsqrtf(s2 * (1.f / DMODEL) + 1e-5f);
    float* orow = out + (size_t)row * DMODEL;
    #pragma unroll
    for (int i = 0; i < 4; i++) {
        int c = tid + i * 256;
        orow[c] = (v[i] - mu) * rstd * w[c] + b[c];
    }
}

// Triangular softmax: row r only processes ceil((r+1)/256)*256 columns.
__global__ void __launch_bounds__(256) softmax_k(float* __restrict__ S) {
    __shared__ float red[8];
    int r = blockIdx.x & (NTOK - 1);
    float* row = S + (long long)blockIdx.x * NTOK;
    int tid = threadIdx.x;
    int nit = (r >> 8) + 1;
    float v[8];
    float mx = -INFINITY;
    #pragma unroll
    for (int i = 0; i < 8; i++) {
        if (i < nit) { v[i] = row[tid + i * 256]; mx = fmaxf(mx, v[i]); }
    }
    mx = blockReduceMax(mx, red);
    float s = 0.f;
    #pragma unroll
    for (int i = 0; i < 8; i++) {
        if (i < nit) { v[i] = expf(v[i] - mx); s += v[i]; }
    }
    s = blockReduceSum(s, red);
    float inv = 1.f / s;
    #pragma unroll
    for (int i = 0; i < 8; i++) {
        if (i < nit) row[tid + i * 256] = v[i] * inv;
    }
}

__global__ void __launch_bounds__(512) router_k(const float* __restrict__ h,
                                                const float* __restrict__ rw,
                                                const float* __restrict__ rb,
                                                int* __restrict__ routes,
                                                float* __restrict__ pmax) {
    __shared__ float lg[NEXP];
    int t = blockIdx.x;
    int wid = threadIdx.x >> 5, lane = threadIdx.x & 31;
    const float* hr = h + (size_t)t * DMODEL;
    const float* wr = rw + (size_t)wid * DMODEL;
    float s = 0.f;
    for (int k = lane; k < DMODEL; k += 32) s += hr[k] * wr[k];
    #pragma unroll
    for (int o = 16; o; o >>= 1) s += __shfl_down_sync(0xffffffffu, s, o);
    if (lane == 0) lg[wid] = s + rb[wid];
    __syncthreads();
    if (threadIdx.x == 0) {
        float mx = lg[0]; int arg = 0;
        #pragma unroll
        for (int e = 1; e < NEXP; e++)
            if (lg[e] > mx) { mx = lg[e]; arg = e; }
        float sum = 0.f;
        #pragma unroll
        for (int e = 0; e < NEXP; e++) sum += expf(lg[e] - mx);
        routes[t] = arg;
        pmax[t] = 1.f / sum;
    }
}

__global__ void __launch_bounds__(512) slot_k(const int* __restrict__ routes,
                                              int* __restrict__ slot,
                                              int* __restrict__ keep) {
    __shared__ int sr[NTOK];
    int tid = threadIdx.x;
    for (int i = tid; i < NTOK; i += 512) sr[i] = routes[i];
    __syncthreads();
    int wid = tid >> 5, lane = tid & 31;
    int pos = 0;
    unsigned lmask = (1u << lane) - 1u;
    for (int base = 0; base < NTOK; base += 32) {
        int r = sr[base + lane];
        unsigned m = __ballot_sync(0xffffffffu, r == wid);
        if (r == wid) {
            int p = pos + __popc(m & lmask);
            int kp = (p < CAP) ? 1 : 0;
            keep[base + lane] = kp;
            slot[base + lane] = kp ? (wid * CAP + p) : (NEXP * CAP);
        }
        pos += __popc(m);
    }
}

__global__ void __launch_bounds__(256) gather_k(const float* __restrict__ h,
                                                const int* __restrict__ slot,
                                                const int* __restrict__ keep,
                                                float* __restrict__ buf) {
    int t = blockIdx.x;
    if (!keep[t]) return;
    int s = slot[t];
    const float4* src = (const float4*)(h + (size_t)t * DMODEL);
    float4* dst = (float4*)(buf + (size_t)s * DMODEL);
    dst[threadIdx.x] = src[threadIdx.x];
}

__global__ void __launch_bounds__(256) final_k(const float* __restrict__ x1,
                                               const float* __restrict__ h2,
                                               const float* __restrict__ ye,
                                               const int* __restrict__ slot,
                                               const int* __restrict__ keep,
                                               const float* __restrict__ pmax,
                                               float* __restrict__ out) {
    int t = blockIdx.x;
    float p = pmax[t];
    const float4* ysrc = keep[t]
        ? (const float4*)(ye + (size_t)slot[t] * DMODEL)
        : (const float4*)(h2 + (size_t)t * DMODEL);
    const float4* xs = (const float4*)(x1 + (size_t)t * DMODEL);
    float4 a = xs[threadIdx.x];
    float4 y = ysrc[threadIdx.x];
    float4 o = make_float4(a.x + y.x * p, a.y + y.y * p, a.z + y.z * p, a.w + y.w * p);
    ((float4*)out)[(size_t)t * (DMODEL / 4) + threadIdx.x] = o;
}

// ---------------------------------------------------------------------------
// Launch
// ---------------------------------------------------------------------------
extern "C" void kernel_launch(void* const* d_in, const int* in_sizes, int n_in,
                              void* d_out, int out_size) {
    const float* x    = (const float*)d_in[0];
    const float* wk   = (const float*)d_in[1];
    const float* bk   = (const float*)d_in[2];
    const float* wq   = (const float*)d_in[3];
    const float* bq   = (const float*)d_in[4];
    const float* wv   = (const float*)d_in[5];
    const float* bv   = (const float*)d_in[6];
    const float* ipw  = (const float*)d_in[7];
    const float* ipb  = (const float*)d_in[8];
    const float* opw  = (const float*)d_in[9];
    const float* opb  = (const float*)d_in[10];
    const float* ln1w = (const float*)d_in[11];
    const float* ln1b = (const float*)d_in[12];
    const float* ln2w = (const float*)d_in[13];
    const float* ln2b = (const float*)d_in[14];
    const float* rw   = (const float*)d_in[15];
    const float* rb   = (const float*)d_in[16];
    const float* w1   = (const float*)d_in[17];
    const float* b1   = (const float*)d_in[18];
    const float* w2   = (const float*)d_in[19];
    const float* b2   = (const float*)d_in[20];
    float* out = (float*)d_out;

    void* sp = nullptr;
    cudaGetSymbolAddress(&sp, g_scratch);
    char* base = (char*)sp;
    float* hln    = (float*)(base + OFF_A);
    float* ctx    = (float*)(base + OFF_A);
    float* qin    = (float*)(base + OFF_B);
    float* x1     = (float*)(base + OFF_B);
    float* h2     = (float*)(base + OFF_C);
    float* q      = (float*)(base + OFF_E);
    float* ye     = (float*)(base + OFF_E);
    float* k      = (float*)(base + OFF_F);
    float* v      = (float*)(base + OFF_G);
    float* buf    = (float*)(base + OFF_G);
    float* sc     = (float*)(base + OFF_SC);
    float* hexp   = (float*)(base + OFF_HEXP);
    float* pakw   = (float*)(base + OFF_PAKW);
    float* pakb   = (float*)(base + OFF_PAKB);
    int*   routes = (int*)(base + OFF_ROUTES);
    int*   slot   = (int*)(base + OFF_SLOT);
    int*   keep   = (int*)(base + OFF_KEEP);
    float* pmax   = (float*)(base + OFF_PMAX);

    // instantiations + dynamic smem opt-in
    //   CH=64 for the BM=128 dense family; CH=32 for PV (TRB) and MoE (BM=160)
    auto GP   = mma_gemm<128, 128, 64, false, true,  false, false, false, false>;  // proj
    auto GPR  = mma_gemm<128, 128, 64, false, true,  false, true,  false, false>;  // out-proj+resid
    auto GQK  = mma_gemm<128, 128, 64, false, false, false, false, true,  false>;  // QK^T masked
    auto GPV  = mma_gemm<64,  64,  32, true,  false, false, false, false, true >;  // P@V causal-trim
    auto GW1  = mma_gemm<160, 128, 32, false, true,  true,  false, false, false>;  // w1+relu
    auto GW2  = mma_gemm<160, 128, 32, false, true,  false, false, false, false>;  // w2
    constexpr int SM128_64 = 2 * (2 * 128 + 2 * 128) * 144;  // 147456
    constexpr int SM64_32  = 2 * (2 * 64  + 2 * 64)  * 80;   // 40960
    constexpr int SM160_32 = 2 * (2 * 160 + 2 * 128) * 80;   // 92160
    cudaFuncSetAttribute(GP,  cudaFuncAttributeMaxDynamicSharedMemorySize, SM128_64);
    cudaFuncSetAttribute(GPR, cudaFuncAttributeMaxDynamicSharedMemorySize, SM128_64);
    cudaFuncSetAttribute(GQK, cudaFuncAttributeMaxDynamicSharedMemorySize, SM128_64);
    cudaFuncSetAttribute(GPV, cudaFuncAttributeMaxDynamicSharedMemorySize, SM64_32);
    cudaFuncSetAttribute(GW1, cudaFuncAttributeMaxDynamicSharedMemorySize, SM160_32);
    cudaFuncSetAttribute(GW2, cudaFuncAttributeMaxDynamicSharedMemorySize, SM160_32);

    // ---- LN1 + weight packing (independent)
    ln_k<<<NTOK, 256>>>(x, ln1w, ln1b, hln);
    pack3_k<<<(3 * DMODEL * DMODEL / 4 + 255) / 256, 256>>>(
        wk, wq, wv, bk, bq, bv, pakw, pakb);

    // ---- first projections: ONE z=3 batched launch
    //      (swapped K/Q per reference: z order wk,wq,wv -> qin,kin,vin)
    dim3 gD3(DMODEL / 128, NTOK / 128, 3);
    GP<<<gD3, 256, SM128_64>>>(hln, pakw, pakb, nullptr, qin,
        NTOK, DMODEL, DMODEL, DMODEL, DMODEL, DMODEL,
        0, (long long)DMODEL * DMODEL, (long long)NTOK * DMODEL, DMODEL);

    // ---- in_proj splits: one batched launch
    GP<<<gD3, 256, SM128_64>>>(qin, ipw, ipb, nullptr, q,
        NTOK, DMODEL, DMODEL, DMODEL, DMODEL, DMODEL,
        (long long)NTOK * DMODEL, (long long)DMODEL * DMODEL,
        (long long)NTOK * DMODEL, DMODEL);

    // ---- attention: groups of HGRP heads, z-batched
    for (int g = 0; g < NHEAD / HGRP; g++) {
        const int ho = g * HGRP * DHEAD;
        dim3 gS(NTOK / 128, NTOK / 128, HGRP);
        GQK<<<gS, 256, SM128_64>>>(q + ho, k + ho, nullptr, nullptr, sc,
            NTOK, NTOK, DHEAD, DMODEL, DMODEL, NTOK,
            DHEAD, DHEAD, (long long)NTOK * NTOK, 0);
        softmax_k<<<HGRP * NTOK, 256>>>(sc);
        dim3 gV(1, NTOK / 64, HGRP);
        GPV<<<gV, 256, SM64_32>>>(sc, v + ho, nullptr, nullptr, ctx + ho,
            NTOK, DHEAD, NTOK, NTOK, DMODEL, DMODEL,
            (long long)NTOK * NTOK, DHEAD, DHEAD, 0);
    }

    // ---- x1 = x + ctx @ opw^T + opb
    dim3 gD(DMODEL / 128, NTOK / 128, 1);
    GPR<<<gD, 256, SM128_64>>>(ctx, opw, opb, x, x1,
        NTOK, DMODEL, DMODEL, DMODEL, DMODEL, DMODEL, 0, 0, 0, 0);

    // ---- LN2
    ln_k<<<NTOK, 256>>>(x1, ln2w, ln2b, h2);

    // ---- router + routing + gather
    router_k<<<NTOK, 512>>>(h2, rw, rb, routes, pmax);
    slot_k<<<1, 512>>>(routes, slot, keep);
    gather_k<<<NTOK, 256>>>(h2, slot, keep, buf);

    // ---- expert FFN layer 1 (relu): single BM=160 launch
    dim3 g1(FEXP / 128, 1, NEXP);
    GW1<<<g1, 256, SM160_32>>>(buf, w1, b1, nullptr, hexp,
        CAP, FEXP, DMODEL, DMODEL, DMODEL, FEXP,
        (long long)CAP * DMODEL, (long long)FEXP * DMODEL,
        (long long)CAP * FEXP, FEXP);

    // ---- expert FFN layer 2: single BM=160 launch
    dim3 g2(DMODEL / 128, 1, NEXP);
    GW2<<<g2, 256, SM160_32>>>(hexp, w2, b2, nullptr, ye,
        CAP, DMODEL, FEXP, FEXP, FEXP, DMODEL,
        (long long)CAP * FEXP, (long long)DMODEL * FEXP,
        (long long)CAP * DMODEL, DMODEL);

    // ---- final combine
    final_k<<<NTOK, 256>>>(x1, h2, ye, slot, keep, pmax, out);
}

// round 16
// speedup vs baseline: 1.4064x; 1.3342x over previous
#include <cuda_runtime.h>
#include <cuda_bf16.h>
#include <math.h>
#include <stdint.h>
#include <string.h>

#define NTOK   2048
#define DMODEL 1024
#define NHEAD  16
#define DHEAD  64
#define FEXP   4096
#define NEXP   16
#define CAP    160      // int(1.25 * 2048 / 16)

// ---------------------------------------------------------------------------
// Scratch (single __device__ bss array; aliased). ~123 MB (scores region kept
// for hexp/pack aliasing; no longer used for scores).
// ---------------------------------------------------------------------------
constexpr size_t SZ_ND = (size_t)NTOK * DMODEL * 4;            // 8 MB
constexpr size_t OFF_A    = 0;               // hln -> ctx
constexpr size_t OFF_B    = 1 * SZ_ND;       // qin -> x1
constexpr size_t OFF_C    = 2 * SZ_ND;       // kin -> h2
constexpr size_t OFF_D    = 3 * SZ_ND;       // vin
constexpr size_t OFF_E    = 4 * SZ_ND;       // q -> ye
constexpr size_t OFF_F    = 5 * SZ_ND;       // k
constexpr size_t OFF_G    = 6 * SZ_ND;       // v -> buf (spills 2.5MB into SC)
constexpr size_t OFF_SC   = 7 * SZ_ND;       // (former scores; hexp/pack live here)
constexpr size_t SZ_SC    = (size_t)4 * NTOK * NTOK * 4;       // 64 MiB kept
constexpr size_t OFF_HEXP = OFF_SC + (size_t)(4 << 20);
constexpr size_t OFF_PAKW = OFF_HEXP;                          // 12 MB
constexpr size_t OFF_PAKB = OFF_PAKW + (size_t)3 * DMODEL * DMODEL * 4;
constexpr size_t OFF_ROUTES = OFF_SC + SZ_SC;
constexpr size_t OFF_SLOT   = OFF_ROUTES + (size_t)NTOK * 4;
constexpr size_t OFF_KEEP   = OFF_SLOT   + (size_t)NTOK * 4;
constexpr size_t OFF_PMAX   = OFF_KEEP   + (size_t)NTOK * 4;
constexpr size_t SCRATCH_BYTES = OFF_PMAX + (size_t)NTOK * 4;

__device__ __align__(256) unsigned char g_scratch[SCRATCH_BYTES];

// ---------------------------------------------------------------------------
// helpers
// ---------------------------------------------------------------------------
__device__ __forceinline__ void mma16816(float* c,
                                         uint32_t a0, uint32_t a1, uint32_t a2, uint32_t a3,
                                         uint32_t b0, uint32_t b1) {
    asm volatile(
        "mma.sync.aligned.m16n8k16.row.col.f32.bf16.bf16.f32 "
        "{%0,%1,%2,%3}, {%4,%5,%6,%7}, {%8,%9}, {%0,%1,%2,%3};"
        : "+f"(c[0]), "+f"(c[1]), "+f"(c[2]), "+f"(c[3])
        : "r"(a0), "r"(a1), "r"(a2), "r"(a3), "r"(b0), "r"(b1));
}

__device__ __forceinline__ void ldsm_x4(uint32_t* r, uint32_t saddr) {
    asm volatile("ldmatrix.sync.aligned.m8n8.x4.shared.b16 {%0,%1,%2,%3}, [%4];"
        : "=r"(r[0]), "=r"(r[1]), "=r"(r[2]), "=r"(r[3]) : "r"(saddr));
}
__device__ __forceinline__ void ldsm_x2(uint32_t* r, uint32_t saddr) {
    asm volatile("ldmatrix.sync.aligned.m8n8.x2.shared.b16 {%0,%1}, [%2];"
        : "=r"(r[0]), "=r"(r[1]) : "r"(saddr));
}

__device__ __forceinline__ uint32_t bf162_bits(float l0, float l1) {
    __nv_bfloat162 p = __floats2bfloat162_rn(l0, l1);
    uint32_t u;
    memcpy(&u, &p, 4);
    return u;
}
__device__ __forceinline__ uint32_t hipack(float a, float b) {
    return (__float_as_uint(a) >> 16) | (__float_as_uint(b) & 0xffff0000u);
}
__device__ __forceinline__ float truncbf(float a) {
    return __uint_as_float(__float_as_uint(a) & 0xffff0000u);
}

// ---------------------------------------------------------------------------
// HMMA GEMM (bf16 trunc-split-2, fp32 accumulate), mma.sync + ldmatrix.
//   C[m,n] = sum_k A[m,k]*B[n,k]  (B K-major)
//   BM in {160,128}; BK=32; BN=128. 256 thr = 8 warps, 1 CTA/SM.
// ---------------------------------------------------------------------------
template<int BM, int BN, bool BIAS, bool RELU, bool RESID>
__global__ void __launch_bounds__(256, 1) mma_gemm(
    const float* __restrict__ A, const float* __restrict__ B,
    const float* __restrict__ bias, const float* __restrict__ resid,
    float* __restrict__ C,
    int M, int Nd, int K, int lda, int ldb, int ldc,
    long long sA, long long sB, long long sC, long long sBias)
{
    constexpr int STR = 80;
    constexpr int WMW = 2;
    constexpr int MT  = BM / (WMW * 16);
    constexpr int WNW = 8 / WMW;
    constexpr int WNSZ = BN / WNW;
    constexpr int NT  = WNSZ / 8;
    constexpr int NA4 = BM / 32;
    constexpr int NB4 = BN / 32;
    constexpr int BUFB = (2 * BM + 2 * BN) * STR;

    extern __shared__ unsigned char dsm[];

    const int tid = threadIdx.x;
    const int wid = tid >> 5, lane = tid & 31;
    const int wm = wid & 1, wn = wid >> 1;
    const int gid = lane >> 2, tig = lane & 3;
    const uint32_t dsm_s = (uint32_t)__cvta_generic_to_shared(dsm);
    const uint32_t laneA = (uint32_t)((lane & 15) * STR + (lane >> 4) * 16);
    const uint32_t laneB = (uint32_t)((lane & 7) * STR + ((lane >> 3) & 1) * 16);

    A += (long long)blockIdx.z * sA;
    B += (long long)blockIdx.z * sB;
    C += (long long)blockIdx.z * sC;
    const float* bptr = nullptr;
    if (BIAS) bptr = bias + (long long)blockIdx.z * sBias;

    const int m0 = blockIdx.y * BM;
    const int n0 = blockIdx.x * BN;

    float acc[MT][NT][4];
    #pragma unroll
    for (int i = 0; i < MT; i++)
        #pragma unroll
        for (int j = 0; j < NT; j++)
            #pragma unroll
            for (int l = 0; l < 4; l++) acc[i][j][l] = 0.f;

    float4 aS[NA4], bS[NB4];

    auto ldA = [&](int k0) {
        #pragma unroll
        for (int i = 0; i < NA4; i++) {
            int j = tid + i * 256;
            int r = j >> 3, c = (j & 7) * 4;
            aS[i] = (m0 + r < M) ? *(const float4*)&A[(long long)(m0 + r) * lda + k0 + c]
                                 : make_float4(0.f, 0.f, 0.f, 0.f);
        }
    };
    auto ldB = [&](int k0) {
        #pragma unroll
        for (int i = 0; i < NB4; i++) {
            int j = tid + i * 256;
            int r = j >> 3, c = (j & 7) * 4;
            bS[i] = (n0 + r < Nd) ? *(const float4*)&B[(long long)(n0 + r) * ldb + k0 + c]
                                  : make_float4(0.f, 0.f, 0.f, 0.f);
        }
    };
    auto stA = [&](unsigned char* bufb) {
        unsigned char* Ah = bufb;
        unsigned char* Al = bufb + BM * STR;
        #pragma unroll
        for (int i = 0; i < NA4; i++) {
            int j = tid + i * 256;
            int r = j >> 3, c4 = j & 7;
            uint4 u;
            memcpy(&u, &aS[i], 16);
            uint32_t h01 = __byte_perm(u.x, u.y, 0x7632);
            uint32_t h23 = __byte_perm(u.z, u.w, 0x7632);
            float l0 = aS[i].x - __uint_as_float(u.x & 0xffff0000u);
            float l1 = aS[i].y - __uint_as_float(u.y & 0xffff0000u);
            float l2 = aS[i].z - __uint_as_float(u.z & 0xffff0000u);
            float l3 = aS[i].w - __uint_as_float(u.w & 0xffff0000u);
            uint32_t off = (uint32_t)(r * STR + c4 * 8);
            *(uint2*)(Ah + off) = make_uint2(h01, h23);
            *(uint2*)(Al + off) = make_uint2(bf162_bits(l0, l1), bf162_bits(l2, l3));
        }
    };
    auto stB = [&](unsigned char* bufb) {
        unsigned char* Bh = bufb + 2 * BM * STR;
        unsigned char* Bl = bufb + 2 * BM * STR + BN * STR;
        #pragma unroll
        for (int i = 0; i < NB4; i++) {
            int j = tid + i * 256;
            int r = j >> 3, c4 = j & 7;
            uint4 u;
            memcpy(&u, &bS[i], 16);
            uint32_t h01 = __byte_perm(u.x, u.y, 0x7632);
            uint32_t h23 = __byte_perm(u.z, u.w, 0x7632);
            float l0 = bS[i].x - __uint_as_float(u.x & 0xffff0000u);
            float l1 = bS[i].y - __uint_as_float(u.y & 0xffff0000u);
            float l2 = bS[i].z - __uint_as_float(u.z & 0xffff0000u);
            float l3 = bS[i].w - __uint_as_float(u.w & 0xffff0000u);
            uint32_t off = (uint32_t)(r * STR + c4 * 8);
            *(uint2*)(Bh + off) = make_uint2(h01, h23);
            *(uint2*)(Bl + off) = make_uint2(bf162_bits(l0, l1), bf162_bits(l2, l3));
        }
    };

    auto compute = [&](uint32_t bufo) {
        const uint32_t AhS = dsm_s + bufo;
        const uint32_t AlS = AhS + BM * STR;
        const uint32_t BhS = dsm_s + bufo + 2 * BM * STR;
        const uint32_t BlS = BhS + BN * STR;
        #pragma unroll
        for (int ks = 0; ks < 2; ks++) {
            const uint32_t kb = (uint32_t)(ks * 32);
            uint32_t a[MT][4], b[NT][2], bl[NT][2];
            #pragma unroll
            for (int ms = 0; ms < MT; ms++)
                ldsm_x4(a[ms], AhS + (uint32_t)((wm * (MT * 16) + ms * 16) * STR) + kb + laneA);
            #pragma unroll
            for (int ns = 0; ns < NT; ns++) {
                uint32_t bo = (uint32_t)((wn * WNSZ + ns * 8) * STR) + kb + laneB;
                ldsm_x2(b[ns],  BhS + bo);
                ldsm_x2(bl[ns], BlS + bo);
            }
            #pragma unroll
            for (int ms = 0; ms < MT; ms++)
                #pragma unroll
                for (int ns = 0; ns < NT; ns++)
                    mma16816(acc[ms][ns], a[ms][0], a[ms][1], a[ms][2], a[ms][3],
                             b[ns][0], b[ns][1]);
            #pragma unroll
            for (int ms = 0; ms < MT; ms++)
                #pragma unroll
                for (int ns = 0; ns < NT; ns++)
                    mma16816(acc[ms][ns], a[ms][0], a[ms][1], a[ms][2], a[ms][3],
                             bl[ns][0], bl[ns][1]);
            #pragma unroll
            for (int ms = 0; ms < MT; ms++)
                ldsm_x4(a[ms], AlS + (uint32_t)((wm * (MT * 16) + ms * 16) * STR) + kb + laneA);
            #pragma unroll
            for (int ms = 0; ms < MT; ms++)
                #pragma unroll
                for (int ns = 0; ns < NT; ns++)
                    mma16816(acc[ms][ns], a[ms][0], a[ms][1], a[ms][2], a[ms][3],
                             b[ns][0], b[ns][1]);
        }
    };

    int nch = K >> 5;
    ldA(0); ldB(0);
    stA(dsm); stB(dsm);
    __syncthreads();
    for (int c = 0; c < nch; c++) {
        if (c + 1 < nch) { ldA((c + 1) << 5); ldB((c + 1) << 5); }
        compute((uint32_t)((c & 1) * BUFB));
        if (c + 1 < nch) {
            unsigned char* nb = dsm + ((c + 1) & 1) * BUFB;
            stA(nb); stB(nb);
        }
        __syncthreads();
    }

    #pragma unroll
    for (int ms = 0; ms < MT; ms++) {
        #pragma unroll
        for (int ns = 0; ns < NT; ns++) {
            int m = m0 + wm * (MT * 16) + ms * 16 + gid;
            int n = n0 + wn * WNSZ + ns * 8 + tig * 2;
            float* cp = acc[ms][ns];
            #pragma unroll
            for (int half = 0; half < 2; half++) {
                int mm = m + half * 8;
                if (mm >= M) continue;
                float v0 = cp[half * 2 + 0], v1 = cp[half * 2 + 1];
                if (BIAS) { v0 += bptr[n]; v1 += bptr[n + 1]; }
                if (RELU) { v0 = fmaxf(v0, 0.f); v1 = fmaxf(v1, 0.f); }
                if (RESID) {
                    float2 rr = *(const float2*)&resid[(long long)mm * ldc + n];
                    v0 += rr.x; v1 += rr.y;
                }
                *(float2*)&C[(long long)mm * ldc + n] = make_float2(v0, v1);
            }
        }
    }
}

// ---------------------------------------------------------------------------
// Fused flash attention: per CTA = (head, 128-query tile). 8 warps; each warp
// owns 16 query rows. Online softmax in registers; K/V staged hi/lo in smem.
// Q/K/P/V all use trunc-split bf16 3-pass mma. scale=0.125, causal mask.
// ---------------------------------------------------------------------------
__global__ void __launch_bounds__(256, 1) fa_k(
    const float* __restrict__ Qg, const float* __restrict__ Kg,
    const float* __restrict__ Vg, float* __restrict__ Octx)
{
    constexpr int STR = 144;                 // 64 bf16 = 128B + 16B pad
    constexpr int QSZ = 128 * STR;           // one Q plane
    constexpr int KSTG = 4 * 64 * STR;       // Kh,Kl,VTh,VTl per stage
    extern __shared__ unsigned char dsm[];

    const int tid = threadIdx.x;
    const int wid = tid >> 5, lane = tid & 31;
    const int gid = lane >> 2, tig = lane & 3;
    const uint32_t dsm_s = (uint32_t)__cvta_generic_to_shared(dsm);
    const uint32_t laneA = (uint32_t)((lane & 15) * STR + (lane >> 4) * 16);
    const uint32_t laneB = (uint32_t)((lane & 7) * STR + ((lane >> 3) & 1) * 16);

    const int head = blockIdx.x;
    const int mt = (NTOK / 128 - 1) - blockIdx.y;   // long tiles scheduled first
    const int m0 = mt * 128;

    const float* qg = Qg + (size_t)head * DHEAD;
    const float* kg = Kg + (size_t)head * DHEAD;
    const float* vg = Vg + (size_t)head * DHEAD;

    // ---- load Q tile 128x64 -> hi/lo smem (once)
    #pragma unroll
    for (int i = 0; i < 8; i++) {
        int j = tid + i * 256;
        int r = j >> 4, c4 = j & 15;
        float4 v = *(const float4*)&qg[(long long)(m0 + r) * DMODEL + c4 * 4];
        uint4 u; memcpy(&u, &v, 16);
        uint32_t h01 = __byte_perm(u.x, u.y, 0x7632);
        uint32_t h23 = __byte_perm(u.z, u.w, 0x7632);
        float l0 = v.x - __uint_as_float(u.x & 0xffff0000u);
        float l1 = v.y - __uint_as_float(u.y & 0xffff0000u);
        float l2 = v.z - __uint_as_float(u.z & 0xffff0000u);
        float l3 = v.w - __uint_as_float(u.w & 0xffff0000u);
        uint32_t off = (uint32_t)(r * STR + c4 * 8);
        *(uint2*)(dsm + off)       = make_uint2(h01, h23);
        *(uint2*)(dsm + QSZ + off) = make_uint2(bf162_bits(l0, l1), bf162_bits(l2, l3));
    }

    const int ntile = 2 * mt + 2;
    float4 kS[4], vS[4];

    auto ldKV = [&](int j) {
        #pragma unroll
        for (int i = 0; i < 4; i++) {
            int jj = tid + i * 256;
            int r = jj >> 4, c4 = jj & 15;
            long long key = (long long)(j * 64 + r);
            kS[i] = *(const float4*)&kg[key * DMODEL + c4 * 4];
            vS[i] = *(const float4*)&vg[key * DMODEL + c4 * 4];
        }
    };
    auto stKV = [&](int s) {
        unsigned char* Kh = dsm + 2 * QSZ + s * KSTG;
        unsigned char* Kl = Kh + 64 * STR;
        unsigned char* Vh = Kh + 2 * 64 * STR;
        unsigned char* Vl = Kh + 3 * 64 * STR;
        #pragma unroll
        for (int i = 0; i < 4; i++) {
            int jj = tid + i * 256;
            int r = jj >> 4, c4 = jj & 15;
            uint4 u; memcpy(&u, &kS[i], 16);
            uint32_t h01 = __byte_perm(u.x, u.y, 0x7632);
            uint32_t h23 = __byte_perm(u.z, u.w, 0x7632);
            float l0 = kS[i].x - __uint_as_float(u.x & 0xffff0000u);
            float l1 = kS[i].y - __uint_as_float(u.y & 0xffff0000u);
            float l2 = kS[i].z - __uint_as_float(u.z & 0xffff0000u);
            float l3 = kS[i].w - __uint_as_float(u.w & 0xffff0000u);
            uint32_t off = (uint32_t)(r * STR + c4 * 8);
            *(uint2*)(Kh + off) = make_uint2(h01, h23);
            *(uint2*)(Kl + off) = make_uint2(bf162_bits(l0, l1), bf162_bits(l2, l3));
            float vv[4] = {vS[i].x, vS[i].y, vS[i].z, vS[i].w};
            #pragma unroll
            for (int q = 0; q < 4; q++) {
                int d = c4 * 4 + q;
                uint32_t ub = __float_as_uint(vv[q]);
                unsigned short h = (unsigned short)(ub >> 16);
                float lof = vv[q] - __uint_as_float(ub & 0xffff0000u);
                unsigned short l = __bfloat16_as_ushort(__float2bfloat16_rn(lof));
                uint32_t off2 = (uint32_t)(d * STR + r * 2);
                *(unsigned short*)(Vh + off2) = h;
                *(unsigned short*)(Vl + off2) = l;
            }
        }
    };

    ldKV(0);
    stKV(0);
    __syncthreads();

    // ---- Q fragments (per warp rows wid*16..wid*16+15)
    uint32_t qh[4][4], qlo[4][4];
    {
        uint32_t qb = dsm_s + (uint32_t)(wid * 16 * STR) + laneA;
        #pragma unroll
        for (int ks = 0; ks < 4; ks++) {
            ldsm_x4(qh[ks],  qb + ks * 32);
            ldsm_x4(qlo[ks], qb + QSZ + ks * 32);
        }
    }

    float o[8][4];
    #pragma unroll
    for (int i = 0; i < 8; i++)
        #pragma unroll
        for (int l = 0; l < 4; l++) o[i][l] = 0.f;
    float mr0 = -INFINITY, mr1 = -INFINITY, lr0 = 0.f, lr1 = 0.f;
    const int row0 = m0 + wid * 16 + gid;
    const int row1 = row0 + 8;

    for (int j = 0; j < ntile; j++) {
        if (j + 1 < ntile) ldKV(j + 1);

        const uint32_t KhS = dsm_s + 2 * QSZ + (uint32_t)((j & 1) * KSTG);
        const uint32_t KlS = KhS + 64 * STR;
        const uint32_t VhS = KhS + 2 * 64 * STR;
        const uint32_t VlS = KhS + 3 * 64 * STR;

        // ---- S = Q K^T (3-pass split)
        float s[8][4];
        #pragma unroll
        for (int nf = 0; nf < 8; nf++) {
            s[nf][0] = s[nf][1] = s[nf][2] = s[nf][3] = 0.f;
            uint32_t bo = (uint32_t)(nf * 8 * STR) + laneB;
            #pragma unroll
            for (int ks = 0; ks < 4; ks++) {
                uint32_t bh[2], bl[2];
                ldsm_x2(bh, KhS + bo + ks * 32);
                ldsm_x2(bl, KlS + bo + ks * 32);
                mma16816(s[nf], qh[ks][0], qh[ks][1], qh[ks][2], qh[ks][3], bh[0], bh[1]);
                mma16816(s[nf], qh[ks][0], qh[ks][1], qh[ks][2], qh[ks][3], bl[0], bl[1]);
                mma16816(s[nf], qlo[ks][0], qlo[ks][1], qlo[ks][2], qlo[ks][3], bh[0], bh[1]);
            }
        }
        // ---- scale + causal mask
        #pragma unroll
        for (int nf = 0; nf < 8; nf++) {
            int c0 = j * 64 + nf * 8 + tig * 2;
            s[nf][0] = (c0     > row0) ? -INFINITY : s[nf][0] * 0.125f;
            s[nf][1] = (c0 + 1 > row0) ? -INFINITY : s[nf][1] * 0.125f;
            s[nf][2] = (c0     > row1) ? -INFINITY : s[nf][2] * 0.125f;
            s[nf][3] = (c0 + 1 > row1) ? -INFINITY : s[nf][3] * 0.125f;
        }
        // ---- row max across nf then quad (tig)
        float mx0 = -INFINITY, mx1 = -INFINITY;
        #pragma unroll
        for (int nf = 0; nf < 8; nf++) {
            mx0 = fmaxf(mx0, fmaxf(s[nf][0], s[nf][1]));
            mx1 = fmaxf(mx1, fmaxf(s[nf][2], s[nf][3]));
        }
        mx0 = fmaxf(mx0, __shfl_xor_sync(0xffffffffu, mx0, 1));
        mx0 = fmaxf(mx0, __shfl_xor_sync(0xffffffffu, mx0, 2));
        mx1 = fmaxf(mx1, __shfl_xor_sync(0xffffffffu, mx1, 1));
        mx1 = fmaxf(mx1, __shfl_xor_sync(0xffffffffu, mx1, 2));
        float mn0 = fmaxf(mr0, mx0), mn1 = fmaxf(mr1, mx1);
        float al0 = expf(mr0 - mn0), al1 = expf(mr1 - mn1);
        // ---- exp + row sums
        float rs0 = 0.f, rs1 = 0.f;
        #pragma unroll
        for (int nf = 0; nf < 8; nf++) {
            s[nf][0] = expf(s[nf][0] - mn0);
            s[nf][1] = expf(s[nf][1] - mn0);
            s[nf][2] = expf(s[nf][2] - mn1);
            s[nf][3] = expf(s[nf][3] - mn1);
            rs0 += s[nf][0] + s[nf][1];
            rs1 += s[nf][2] + s[nf][3];
        }
        rs0 += __shfl_xor_sync(0xffffffffu, rs0, 1);
        rs0 += __shfl_xor_sync(0xffffffffu, rs0, 2);
        rs1 += __shfl_xor_sync(0xffffffffu, rs1, 1);
        rs1 += __shfl_xor_sync(0xffffffffu, rs1, 2);
        lr0 = lr0 * al0 + rs0;
        lr1 = lr1 * al1 + rs1;
        mr0 = mn0; mr1 = mn1;
        // ---- rescale O
        #pragma unroll
        for (int df = 0; df < 8; df++) {
            o[df][0] *= al0; o[df][1] *= al0;
            o[df][2] *= al1; o[df][3] *= al1;
        }
        // ---- O += P V  (P from S frags, split hi/lo; 3-pass)
        #pragma unroll
        for (int ks = 0; ks < 4; ks++) {
            float* f0 = s[2 * ks];
            float* f1 = s[2 * ks + 1];
            uint32_t ah[4], alo[4];
            ah[0] = hipack(f0[0], f0[1]);  ah[1] = hipack(f0[2], f0[3]);
            ah[2] = hipack(f1[0], f1[1]);  ah[3] = hipack(f1[2], f1[3]);
            alo[0] = bf162_bits(f0[0] - truncbf(f0[0]), f0[1] - truncbf(f0[1]));
            alo[1] = bf162_bits(f0[2] - truncbf(f0[2]), f0[3] - truncbf(f0[3]));
            alo[2] = bf162_bits(f1[0] - truncbf(f1[0]), f1[1] - truncbf(f1[1]));
            alo[3] = bf162_bits(f1[2] - truncbf(f1[2]), f1[3] - truncbf(f1[3]));
            #pragma unroll
            for (int df = 0; df < 8; df++) {
                uint32_t bo = (uint32_t)(df * 8 * STR) + laneB + ks * 32;
                uint32_t bh[2], bl[2];
                ldsm_x2(bh, VhS + bo);
                ldsm_x2(bl, VlS + bo);
                mma16816(o[df], ah[0], ah[1], ah[2], ah[3], bh[0], bh[1]);
                mma16816(o[df], alo[0], alo[1], alo[2], alo[3], bh[0], bh[1]);
                mma16816(o[df], ah[0], ah[1], ah[2], ah[3], bl[0], bl[1]);
            }
        }

        if (j + 1 < ntile) stKV((j + 1) & 1);
        __syncthreads();
    }

    // ---- epilogue: O / l -> ctx
    float inv0 = 1.f / lr0, inv1 = 1.f / lr1;
    #pragma unroll
    for (int df = 0; df < 8; df++) {
        int col = head * DHEAD + df * 8 + tig * 2;
        *(float2*)&Octx[(long long)row0 * DMODEL + col] =
            make_float2(o[df][0] * inv0, o[df][1] * inv0);
        *(float2*)&Octx[(long long)row1 * DMODEL + col] =
            make_float2(o[df][2] * inv1, o[df][3] * inv1);
    }
}

// ---------------------------------------------------------------------------
// Pack wk|wq|wv and bk|bq|bv into contiguous scratch for one z=3 launch
// ---------------------------------------------------------------------------
__global__ void __launch_bounds__(256) pack3_k(
    const float* __restrict__ a0, const float* __restrict__ a1, const float* __restrict__ a2,
    const float* __restrict__ b0, const float* __restrict__ b1, const float* __restrict__ b2,
    float* __restrict__ w, float* __restrict__ b)
{
    constexpr int N4 = DMODEL * DMODEL / 4;
    int idx = blockIdx.x * 256 + threadIdx.x;
    if (idx < 3 * N4) {
        const float* src = (idx < N4) ? a0 : (idx < 2 * N4) ? a1 : a2;
        int loc = idx - (idx < N4 ? 0 : (idx < 2 * N4 ? N4 : 2 * N4));
        ((float4*)w)[idx] = ((const float4*)src)[loc];
    }
    if (idx < 3 * DMODEL / 4) {
        constexpr int B4 = DMODEL / 4;
        const float* src = (idx < B4) ? b0 : (idx < 2 * B4) ? b1 : b2;
        int loc = idx - (idx < B4 ? 0 : (idx < 2 * B4 ? B4 : 2 * B4));
        ((float4*)b)[idx] = ((const float4*)src)[loc];
    }
}

// ---------------------------------------------------------------------------
// Block reductions + glue kernels
// ---------------------------------------------------------------------------
__device__ __forceinline__ float blockReduceSum(float val, float* red) {
    int lane = threadIdx.x & 31, wid = threadIdx.x >> 5;
    #pragma unroll
    for (int o = 16; o; o >>= 1) val += __shfl_down_sync(0xffffffffu, val, o);
    __syncthreads();
    if (lane == 0) red[wid] = val;
    __syncthreads();
    if (threadIdx.x < 32) {
        val = (lane < 8) ? red[lane] : 0.f;
        #pragma unroll
        for (int o = 4; o; o >>= 1) val += __shfl_down_sync(0xffffffffu, val, o);
        if (lane == 0) red[0] = val;
    }
    __syncthreads();
    return red[0];
}

__global__ void __launch_bounds__(256) ln_k(const float* __restrict__ x,
                                            const float* __restrict__ w,
                                            const float* __restrict__ b,
                                            float* __restrict__ out) {
    __shared__ float red[8];
    int row = blockIdx.x, tid = threadIdx.x;
    const float* xr = x + (size_t)row * DMODEL;
    float v[4];
    float s = 0.f;
    #pragma unroll
    for (int i = 0; i < 4; i++) { v[i] = xr[tid + i * 256]; s += v[i]; }
    s = blockReduceSum(s, red);
    float mu = s * (1.f / DMODEL);
    float s2 = 0.f;
    #pragma unroll
    for (int i = 0; i < 4; i++) { float d = v[i] - mu; s2 += d * d; }
    s2 = blockReduceSum(s2, red);
    float rstd = rsqrtf(s2 * (1.f / DMODEL) + 1e-5f);
    float* orow = out + (size_t)row * DMODEL;
    #pragma unroll
    for (int i = 0; i < 4; i++) {
        int c = tid + i * 256;
        orow[c] = (v[i] - mu) * rstd * w[c] + b[c];
    }
}

__global__ void __launch_bounds__(512) router_k(const float* __restrict__ h,
                                                const float* __restrict__ rw,
                                                const float* __restrict__ rb,
                                                int* __restrict__ routes,
                                                float* __restrict__ pmax) {
    __shared__ float lg[NEXP];
    int t = blockIdx.x;
    int wid = threadIdx.x >> 5, lane = threadIdx.x & 31;
    const float* hr = h + (size_t)t * DMODEL;
    const float* wr = rw + (size_t)wid * DMODEL;
    float s = 0.f;
    for (int k = lane; k < DMODEL; k += 32) s += hr[k] * wr[k];
    #pragma unroll
    for (int o = 16; o; o >>= 1) s += __shfl_down_sync(0xffffffffu, s, o);
    if (lane == 0) lg[wid] = s + rb[wid];
    __syncthreads();
    if (threadIdx.x == 0) {
        float mx = lg[0]; int arg = 0;
        #pragma unroll
        for (int e = 1; e < NEXP; e++)
            if (lg[e] > mx) { mx = lg[e]; arg = e; }
        float sum = 0.f;
        #pragma unroll
        for (int e = 0; e < NEXP; e++) sum += expf(lg[e] - mx);
        routes[t] = arg;
        pmax[t] = 1.f / sum;
    }
}

__global__ void __launch_bounds__(512) slot_k(const int* __restrict__ routes,
                                              int* __restrict__ slot,
                                              int* __restrict__ keep) {
    __shared__ int sr[NTOK];
    int tid = threadIdx.x;
    for (int i = tid; i < NTOK; i += 512) sr[i] = routes[i];
    __syncthreads();
    int wid = tid >> 5, lane = tid & 31;
    int pos = 0;
    unsigned lmask = (1u << lane) - 1u;
    for (int base = 0; base < NTOK; base += 32) {
        int r = sr[base + lane];
        unsigned m = __ballot_sync(0xffffffffu, r == wid);
        if (r == wid) {
            int p = pos + __popc(m & lmask);
            int kp = (p < CAP) ? 1 : 0;
            keep[base + lane] = kp;
            slot[base + lane] = kp ? (wid * CAP + p) : (NEXP * CAP);
        }
        pos += __popc(m);
    }
}

__global__ void __launch_bounds__(256) gather_k(const float* __restrict__ h,
                                                const int* __restrict__ slot,
                                                const int* __restrict__ keep,
                                                float* __restrict__ buf) {
    int t = blockIdx.x;
    if (!keep[t]) return;
    int s = slot[t];
    const float4* src = (const float4*)(h + (size_t)t * DMODEL);
    float4* dst = (float4*)(buf + (size_t)s * DMODEL);
    dst[threadIdx.x] = src[threadIdx.x];
}

__global__ void __launch_bounds__(256) final_k(const float* __restrict__ x1,
                                               const float* __restrict__ h2,
                                               const float* __restrict__ ye,
                                               const int* __restrict__ slot,
                                               const int* __restrict__ keep,
                                               const float* __restrict__ pmax,
                                               float* __restrict__ out) {
    int t = blockIdx.x;
    float p = pmax[t];
    const float4* ysrc = keep[t]
        ? (const float4*)(ye + (size_t)slot[t] * DMODEL)
        : (const float4*)(h2 + (size_t)t * DMODEL);
    const float4* xs = (const float4*)(x1 + (size_t)t * DMODEL);
    float4 a = xs[threadIdx.x];
    float4 y = ysrc[threadIdx.x];
    float4 o = make_float4(a.x + y.x * p, a.y + y.y * p, a.z + y.z * p, a.w + y.w * p);
    ((float4*)out)[(size_t)t * (DMODEL / 4) + threadIdx.x] = o;
}

// ---------------------------------------------------------------------------
// Launch
// ---------------------------------------------------------------------------
extern "C" void kernel_launch(void* const* d_in, const int* in_sizes, int n_in,
                              void* d_out, int out_size) {
    const float* x    = (const float*)d_in[0];
    const float* wk   = (const float*)d_in[1];
    const float* bk   = (const float*)d_in[2];
    const float* wq   = (const float*)d_in[3];
    const float* bq   = (const float*)d_in[4];
    const float* wv   = (const float*)d_in[5];
    const float* bv   = (const float*)d_in[6];
    const float* ipw  = (const float*)d_in[7];
    const float* ipb  = (const float*)d_in[8];
    const float* opw  = (const float*)d_in[9];
    const float* opb  = (const float*)d_in[10];
    const float* ln1w = (const float*)d_in[11];
    const float* ln1b = (const float*)d_in[12];
    const float* ln2w = (const float*)d_in[13];
    const float* ln2b = (const float*)d_in[14];
    const float* rw   = (const float*)d_in[15];
    const float* rb   = (const float*)d_in[16];
    const float* w1   = (const float*)d_in[17];
    const float* b1   = (const float*)d_in[18];
    const float* w2   = (const float*)d_in[19];
    const float* b2   = (const float*)d_in[20];
    float* out = (float*)d_out;

    void* sp = nullptr;
    cudaGetSymbolAddress(&sp, g_scratch);
    char* base = (char*)sp;
    float* hln    = (float*)(base + OFF_A);
    float* ctx    = (float*)(base + OFF_A);
    float* qin    = (float*)(base + OFF_B);
    float* x1     = (float*)(base + OFF_B);
    float* h2     = (float*)(base + OFF_C);
    float* q      = (float*)(base + OFF_E);
    float* ye     = (float*)(base + OFF_E);
    float* k      = (float*)(base + OFF_F);
    float* v      = (float*)(base + OFF_G);
    float* buf    = (float*)(base + OFF_G);
    float* hexp   = (float*)(base + OFF_HEXP);
    float* pakw   = (float*)(base + OFF_PAKW);
    float* pakb   = (float*)(base + OFF_PAKB);
    int*   routes = (int*)(base + OFF_ROUTES);
    int*   slot   = (int*)(base + OFF_SLOT);
    int*   keep   = (int*)(base + OFF_KEEP);
    float* pmax   = (float*)(base + OFF_PMAX);

    auto GP   = mma_gemm<128, 128, true,  false, false>;  // proj
    auto GPR  = mma_gemm<128, 128, true,  false, true >;  // out-proj+resid
    auto GW1  = mma_gemm<160, 128, true,  true,  false>;  // w1+relu
    auto GW2  = mma_gemm<160, 128, true,  false, false>;  // w2
    constexpr int SM128 = 2 * (2 * 128 + 2 * 128) * 80;   // 81920
    constexpr int SM160 = 2 * (2 * 160 + 2 * 128) * 80;   // 92160
    constexpr int SMFA  = 2 * 128 * 144 + 2 * 4 * 64 * 144;  // 110592
    cudaFuncSetAttribute(GP,   cudaFuncAttributeMaxDynamicSharedMemorySize, SM128);
    cudaFuncSetAttribute(GPR,  cudaFuncAttributeMaxDynamicSharedMemorySize, SM128);
    cudaFuncSetAttribute(GW1,  cudaFuncAttributeMaxDynamicSharedMemorySize, SM160);
    cudaFuncSetAttribute(GW2,  cudaFuncAttributeMaxDynamicSharedMemorySize, SM160);
    cudaFuncSetAttribute(fa_k, cudaFuncAttributeMaxDynamicSharedMemorySize, SMFA);

    // ---- LN1 + weight packing (independent)
    ln_k<<<NTOK, 256>>>(x, ln1w, ln1b, hln);
    pack3_k<<<(3 * DMODEL * DMODEL / 4 + 255) / 256, 256>>>(
        wk, wq, wv, bk, bq, bv, pakw, pakb);

    // ---- first projections: ONE z=3 batched launch
    //      (swapped K/Q per reference: z order wk,wq,wv -> qin,kin,vin)
    dim3 gD3(DMODEL / 128, NTOK / 128, 3);
    GP<<<gD3, 256, SM128>>>(hln, pakw, pakb, nullptr, qin,
        NTOK, DMODEL, DMODEL, DMODEL, DMODEL, DMODEL,
        0, (long long)DMODEL * DMODEL, (long long)NTOK * DMODEL, DMODEL);

    // ---- in_proj splits: one batched launch
    GP<<<gD3, 256, SM128>>>(qin, ipw, ipb, nullptr, q,
        NTOK, DMODEL, DMODEL, DMODEL, DMODEL, DMODEL,
        (long long)NTOK * DMODEL, (long long)DMODEL * DMODEL,
        (long long)NTOK * DMODEL, DMODEL);

    // ---- fused flash attention: one launch, 256 CTAs
    dim3 gFA(NHEAD, NTOK / 128);
    fa_k<<<gFA, 256, SMFA>>>(q, k, v, ctx);

    // ---- x1 = x + ctx @ opw^T + opb
    dim3 gD(DMODEL / 128, NTOK / 128, 1);
    GPR<<<gD, 256, SM128>>>(ctx, opw, opb, x, x1,
        NTOK, DMODEL, DMODEL, DMODEL, DMODEL, DMODEL, 0, 0, 0, 0);

    // ---- LN2
    ln_k<<<NTOK, 256>>>(x1, ln2w, ln2b, h2);

    // ---- router + routing + gather
    router_k<<<NTOK, 512>>>(h2, rw, rb, routes, pmax);
    slot_k<<<1, 512>>>(routes, slot, keep);
    gather_k<<<NTOK, 256>>>(h2, slot, keep, buf);

    // ---- expert FFN layer 1 (relu): single BM=160 launch
    dim3 g1(FEXP / 128, 1, NEXP);
    GW1<<<g1, 256, SM160>>>(buf, w1, b1, nullptr, hexp,
        CAP, FEXP, DMODEL, DMODEL, DMODEL, FEXP,
        (long long)CAP * DMODEL, (long long)FEXP * DMODEL,
        (long long)CAP * FEXP, FEXP);

    // ---- expert FFN layer 2: single BM=160 launch
    dim3 g2(DMODEL / 128, 1, NEXP);
    GW2<<<g2, 256, SM160>>>(hexp, w2, b2, nullptr, ye,
        CAP, DMODEL, FEXP, FEXP, FEXP, DMODEL,
        (long long)CAP * FEXP, (long long)DMODEL * FEXP,
        (long long)CAP * DMODEL, DMODEL);

    // ---- final combine
    final_k<<<NTOK, 256>>>(x1, h2, ye, slot, keep, pmax, out);
}

// round 17
// speedup vs baseline: 1.4756x; 1.0492x over previous
#include <cuda_runtime.h>
#include <cuda_bf16.h>
#include <math.h>
#include <stdint.h>
#include <string.h>

#define NTOK   2048
#define DMODEL 1024
#define NHEAD  16
#define DHEAD  64
#define FEXP   4096
#define NEXP   16
#define CAP    160      // int(1.25 * 2048 / 16)

// ---------------------------------------------------------------------------
// Scratch (single __device__ bss array; aliased). ~123 MB.
// ---------------------------------------------------------------------------
constexpr size_t SZ_ND = (size_t)NTOK * DMODEL * 4;            // 8 MB
constexpr size_t OFF_A    = 0;               // hln -> ctx
constexpr size_t OFF_B    = 1 * SZ_ND;       // x1
constexpr size_t OFF_C    = 2 * SZ_ND;       // h2
constexpr size_t OFF_D    = 3 * SZ_ND;       // (spare)
constexpr size_t OFF_E    = 4 * SZ_ND;       // q -> ye
constexpr size_t OFF_F    = 5 * SZ_ND;       // k
constexpr size_t OFF_G    = 6 * SZ_ND;       // v -> buf (spills 2.5MB into SC)
constexpr size_t OFF_SC   = 7 * SZ_ND;       // region: pack/combine then hexp
constexpr size_t SZ_SC    = (size_t)4 * NTOK * NTOK * 4;       // 64 MiB kept
constexpr size_t SZ_MAT   = (size_t)DMODEL * DMODEL;           // 1M elts
constexpr size_t OFF_HEXP = OFF_SC + (size_t)(4 << 20);
constexpr size_t OFF_PAKW = OFF_HEXP;                          // 12 MB (wT packed)
constexpr size_t OFF_WCMB = OFF_PAKW + 3 * SZ_MAT * 4;         // 12 MB combined W
constexpr size_t OFF_PAKB = OFF_WCMB + 3 * SZ_MAT * 4;
constexpr size_t OFF_BCMB = OFF_PAKB + (size_t)3 * DMODEL * 4;
constexpr size_t OFF_ROUTES = OFF_SC + SZ_SC;
constexpr size_t OFF_SLOT   = OFF_ROUTES + (size_t)NTOK * 4;
constexpr size_t OFF_KEEP   = OFF_SLOT   + (size_t)NTOK * 4;
constexpr size_t OFF_PMAX   = OFF_KEEP   + (size_t)NTOK * 4;
constexpr size_t SCRATCH_BYTES = OFF_PMAX + (size_t)NTOK * 4;

__device__ __align__(256) unsigned char g_scratch[SCRATCH_BYTES];

// ---------------------------------------------------------------------------
// helpers
// ---------------------------------------------------------------------------
__device__ __forceinline__ void mma16816(float* c,
                                         uint32_t a0, uint32_t a1, uint32_t a2, uint32_t a3,
                                         uint32_t b0, uint32_t b1) {
    asm volatile(
        "mma.sync.aligned.m16n8k16.row.col.f32.bf16.bf16.f32 "
        "{%0,%1,%2,%3}, {%4,%5,%6,%7}, {%8,%9}, {%0,%1,%2,%3};"
        : "+f"(c[0]), "+f"(c[1]), "+f"(c[2]), "+f"(c[3])
        : "r"(a0), "r"(a1), "r"(a2), "r"(a3), "r"(b0), "r"(b1));
}

__device__ __forceinline__ void ldsm_x4(uint32_t* r, uint32_t saddr) {
    asm volatile("ldmatrix.sync.aligned.m8n8.x4.shared.b16 {%0,%1,%2,%3}, [%4];"
        : "=r"(r[0]), "=r"(r[1]), "=r"(r[2]), "=r"(r[3]) : "r"(saddr));
}
__device__ __forceinline__ void ldsm_x2(uint32_t* r, uint32_t saddr) {
    asm volatile("ldmatrix.sync.aligned.m8n8.x2.shared.b16 {%0,%1}, [%2];"
        : "=r"(r[0]), "=r"(r[1]) : "r"(saddr));
}

__device__ __forceinline__ uint32_t bf162_bits(float l0, float l1) {
    __nv_bfloat162 p = __floats2bfloat162_rn(l0, l1);
    uint32_t u;
    memcpy(&u, &p, 4);
    return u;
}
__device__ __forceinline__ uint32_t hipack(float a, float b) {
    return (__float_as_uint(a) >> 16) | (__float_as_uint(b) & 0xffff0000u);
}
__device__ __forceinline__ float truncbf(float a) {
    return __uint_as_float(__float_as_uint(a) & 0xffff0000u);
}

// ---------------------------------------------------------------------------
// HMMA GEMM (bf16 trunc-split-2, fp32 accumulate), mma.sync + ldmatrix.
//   C[m,n] = sum_k A[m,k]*B[n,k]  (B K-major)
//   BM in {160,128}; BK=32; BN=128. 256 thr = 8 warps, 1 CTA/SM.
// ---------------------------------------------------------------------------
template<int BM, int BN, bool BIAS, bool RELU, bool RESID>
__global__ void __launch_bounds__(256, 1) mma_gemm(
    const float* __restrict__ A, const float* __restrict__ B,
    const float* __restrict__ bias, const float* __restrict__ resid,
    float* __restrict__ C,
    int M, int Nd, int K, int lda, int ldb, int ldc,
    long long sA, long long sB, long long sC, long long sBias)
{
    constexpr int STR = 80;
    constexpr int WMW = 2;
    constexpr int MT  = BM / (WMW * 16);
    constexpr int WNW = 8 / WMW;
    constexpr int WNSZ = BN / WNW;
    constexpr int NT  = WNSZ / 8;
    constexpr int NA4 = BM / 32;
    constexpr int NB4 = BN / 32;
    constexpr int BUFB = (2 * BM + 2 * BN) * STR;

    extern __shared__ unsigned char dsm[];

    const int tid = threadIdx.x;
    const int wid = tid >> 5, lane = tid & 31;
    const int wm = wid & 1, wn = wid >> 1;
    const int gid = lane >> 2, tig = lane & 3;
    const uint32_t dsm_s = (uint32_t)__cvta_generic_to_shared(dsm);
    const uint32_t laneA = (uint32_t)((lane & 15) * STR + (lane >> 4) * 16);
    const uint32_t laneB = (uint32_t)((lane & 7) * STR + ((lane >> 3) & 1) * 16);

    A += (long long)blockIdx.z * sA;
    B += (long long)blockIdx.z * sB;
    C += (long long)blockIdx.z * sC;
    const float* bptr = nullptr;
    if (BIAS) bptr = bias + (long long)blockIdx.z * sBias;

    const int m0 = blockIdx.y * BM;
    const int n0 = blockIdx.x * BN;

    float acc[MT][NT][4];
    #pragma unroll
    for (int i = 0; i < MT; i++)
        #pragma unroll
        for (int j = 0; j < NT; j++)
            #pragma unroll
            for (int l = 0; l < 4; l++) acc[i][j][l] = 0.f;

    float4 aS[NA4], bS[NB4];

    auto ldA = [&](int k0) {
        #pragma unroll
        for (int i = 0; i < NA4; i++) {
            int j = tid + i * 256;
            int r = j >> 3, c = (j & 7) * 4;
            aS[i] = (m0 + r < M) ? *(const float4*)&A[(long long)(m0 + r) * lda + k0 + c]
                                 : make_float4(0.f, 0.f, 0.f, 0.f);
        }
    };
    auto ldB = [&](int k0) {
        #pragma unroll
        for (int i = 0; i < NB4; i++) {
            int j = tid + i * 256;
            int r = j >> 3, c = (j & 7) * 4;
            bS[i] = (n0 + r < Nd) ? *(const float4*)&B[(long long)(n0 + r) * ldb + k0 + c]
                                  : make_float4(0.f, 0.f, 0.f, 0.f);
        }
    };
    auto stA = [&](unsigned char* bufb) {
        unsigned char* Ah = bufb;
        unsigned char* Al = bufb + BM * STR;
        #pragma unroll
        for (int i = 0; i < NA4; i++) {
            int j = tid + i * 256;
            int r = j >> 3, c4 = j & 7;
            uint4 u;
            memcpy(&u, &aS[i], 16);
            uint32_t h01 = __byte_perm(u.x, u.y, 0x7632);
            uint32_t h23 = __byte_perm(u.z, u.w, 0x7632);
            float l0 = aS[i].x - __uint_as_float(u.x & 0xffff0000u);
            float l1 = aS[i].y - __uint_as_float(u.y & 0xffff0000u);
            float l2 = aS[i].z - __uint_as_float(u.z & 0xffff0000u);
            float l3 = aS[i].w - __uint_as_float(u.w & 0xffff0000u);
            uint32_t off = (uint32_t)(r * STR + c4 * 8);
            *(uint2*)(Ah + off) = make_uint2(h01, h23);
            *(uint2*)(Al + off) = make_uint2(bf162_bits(l0, l1), bf162_bits(l2, l3));
        }
    };
    auto stB = [&](unsigned char* bufb) {
        unsigned char* Bh = bufb + 2 * BM * STR;
        unsigned char* Bl = bufb + 2 * BM * STR + BN * STR;
        #pragma unroll
        for (int i = 0; i < NB4; i++) {
            int j = tid + i * 256;
            int r = j >> 3, c4 = j & 7;
            uint4 u;
            memcpy(&u, &bS[i], 16);
            uint32_t h01 = __byte_perm(u.x, u.y, 0x7632);
            uint32_t h23 = __byte_perm(u.z, u.w, 0x7632);
            float l0 = bS[i].x - __uint_as_float(u.x & 0xffff0000u);
            float l1 = bS[i].y - __uint_as_float(u.y & 0xffff0000u);
            float l2 = bS[i].z - __uint_as_float(u.z & 0xffff0000u);
            float l3 = bS[i].w - __uint_as_float(u.w & 0xffff0000u);
            uint32_t off = (uint32_t)(r * STR + c4 * 8);
            *(uint2*)(Bh + off) = make_uint2(h01, h23);
            *(uint2*)(Bl + off) = make_uint2(bf162_bits(l0, l1), bf162_bits(l2, l3));
        }
    };

    auto compute = [&](uint32_t bufo) {
        const uint32_t AhS = dsm_s + bufo;
        const uint32_t AlS = AhS + BM * STR;
        const uint32_t BhS = dsm_s + bufo + 2 * BM * STR;
        const uint32_t BlS = BhS + BN * STR;
        #pragma unroll
        for (int ks = 0; ks < 2; ks++) {
            const uint32_t kb = (uint32_t)(ks * 32);
            uint32_t a[MT][4], b[NT][2], bl[NT][2];
            #pragma unroll
            for (int ms = 0; ms < MT; ms++)
                ldsm_x4(a[ms], AhS + (uint32_t)((wm * (MT * 16) + ms * 16) * STR) + kb + laneA);
            #pragma unroll
            for (int ns = 0; ns < NT; ns++) {
                uint32_t bo = (uint32_t)((wn * WNSZ + ns * 8) * STR) + kb + laneB;
                ldsm_x2(b[ns],  BhS + bo);
                ldsm_x2(bl[ns], BlS + bo);
            }
            #pragma unroll
            for (int ms = 0; ms < MT; ms++)
                #pragma unroll
                for (int ns = 0; ns < NT; ns++)
                    mma16816(acc[ms][ns], a[ms][0], a[ms][1], a[ms][2], a[ms][3],
                             b[ns][0], b[ns][1]);
            #pragma unroll
            for (int ms = 0; ms < MT; ms++)
                #pragma unroll
                for (int ns = 0; ns < NT; ns++)
                    mma16816(acc[ms][ns], a[ms][0], a[ms][1], a[ms][2], a[ms][3],
                             bl[ns][0], bl[ns][1]);
            #pragma unroll
            for (int ms = 0; ms < MT; ms++)
                ldsm_x4(a[ms], AlS + (uint32_t)((wm * (MT * 16) + ms * 16) * STR) + kb + laneA);
            #pragma unroll
            for (int ms = 0; ms < MT; ms++)
                #pragma unroll
                for (int ns = 0; ns < NT; ns++)
                    mma16816(acc[ms][ns], a[ms][0], a[ms][1], a[ms][2], a[ms][3],
                             b[ns][0], b[ns][1]);
        }
    };

    int nch = K >> 5;
    ldA(0); ldB(0);
    stA(dsm); stB(dsm);
    __syncthreads();
    for (int c = 0; c < nch; c++) {
        if (c + 1 < nch) { ldA((c + 1) << 5); ldB((c + 1) << 5); }
        compute((uint32_t)((c & 1) * BUFB));
        if (c + 1 < nch) {
            unsigned char* nb = dsm + ((c + 1) & 1) * BUFB;
            stA(nb); stB(nb);
        }
        __syncthreads();
    }

    #pragma unroll
    for (int ms = 0; ms < MT; ms++) {
        #pragma unroll
        for (int ns = 0; ns < NT; ns++) {
            int m = m0 + wm * (MT * 16) + ms * 16 + gid;
            int n = n0 + wn * WNSZ + ns * 8 + tig * 2;
            float* cp = acc[ms][ns];
            #pragma unroll
            for (int half = 0; half < 2; half++) {
                int mm = m + half * 8;
                if (mm >= M) continue;
                float v0 = cp[half * 2 + 0], v1 = cp[half * 2 + 1];
                if (BIAS) { v0 += bptr[n]; v1 += bptr[n + 1]; }
                if (RELU) { v0 = fmaxf(v0, 0.f); v1 = fmaxf(v1, 0.f); }
                if (RESID) {
                    float2 rr = *(const float2*)&resid[(long long)mm * ldc + n];
                    v0 += rr.x; v1 += rr.y;
                }
                *(float2*)&C[(long long)mm * ldc + n] = make_float2(v0, v1);
            }
        }
    }
}

// ---------------------------------------------------------------------------
// Fused flash attention (unchanged from round 16)
// ---------------------------------------------------------------------------
__global__ void __launch_bounds__(256, 1) fa_k(
    const float* __restrict__ Qg, const float* __restrict__ Kg,
    const float* __restrict__ Vg, float* __restrict__ Octx)
{
    constexpr int STR = 144;
    constexpr int QSZ = 128 * STR;
    constexpr int KSTG = 4 * 64 * STR;
    extern __shared__ unsigned char dsm[];

    const int tid = threadIdx.x;
    const int wid = tid >> 5, lane = tid & 31;
    const int gid = lane >> 2, tig = lane & 3;
    const uint32_t dsm_s = (uint32_t)__cvta_generic_to_shared(dsm);
    const uint32_t laneA = (uint32_t)((lane & 15) * STR + (lane >> 4) * 16);
    const uint32_t laneB = (uint32_t)((lane & 7) * STR + ((lane >> 3) & 1) * 16);

    const int head = blockIdx.x;
    const int mt = (NTOK / 128 - 1) - blockIdx.y;
    const int m0 = mt * 128;

    const float* qg = Qg + (size_t)head * DHEAD;
    const float* kg = Kg + (size_t)head * DHEAD;
    const float* vg = Vg + (size_t)head * DHEAD;

    #pragma unroll
    for (int i = 0; i < 8; i++) {
        int j = tid + i * 256;
        int r = j >> 4, c4 = j & 15;
        float4 v = *(const float4*)&qg[(long long)(m0 + r) * DMODEL + c4 * 4];
        uint4 u; memcpy(&u, &v, 16);
        uint32_t h01 = __byte_perm(u.x, u.y, 0x7632);
        uint32_t h23 = __byte_perm(u.z, u.w, 0x7632);
        float l0 = v.x - __uint_as_float(u.x & 0xffff0000u);
        float l1 = v.y - __uint_as_float(u.y & 0xffff0000u);
        float l2 = v.z - __uint_as_float(u.z & 0xffff0000u);
        float l3 = v.w - __uint_as_float(u.w & 0xffff0000u);
        uint32_t off = (uint32_t)(r * STR + c4 * 8);
        *(uint2*)(dsm + off)       = make_uint2(h01, h23);
        *(uint2*)(dsm + QSZ + off) = make_uint2(bf162_bits(l0, l1), bf162_bits(l2, l3));
    }

    const int ntile = 2 * mt + 2;
    float4 kS[4], vS[4];

    auto ldKV = [&](int j) {
        #pragma unroll
        for (int i = 0; i < 4; i++) {
            int jj = tid + i * 256;
            int r = jj >> 4, c4 = jj & 15;
            long long key = (long long)(j * 64 + r);
            kS[i] = *(const float4*)&kg[key * DMODEL + c4 * 4];
            vS[i] = *(const float4*)&vg[key * DMODEL + c4 * 4];
        }
    };
    auto stKV = [&](int s) {
        unsigned char* Kh = dsm + 2 * QSZ + s * KSTG;
        unsigned char* Kl = Kh + 64 * STR;
        unsigned char* Vh = Kh + 2 * 64 * STR;
        unsigned char* Vl = Kh + 3 * 64 * STR;
        #pragma unroll
        for (int i = 0; i < 4; i++) {
            int jj = tid + i * 256;
            int r = jj >> 4, c4 = jj & 15;
            uint4 u; memcpy(&u, &kS[i], 16);
            uint32_t h01 = __byte_perm(u.x, u.y, 0x7632);
            uint32_t h23 = __byte_perm(u.z, u.w, 0x7632);
            float l0 = kS[i].x - __uint_as_float(u.x & 0xffff0000u);
            float l1 = kS[i].y - __uint_as_float(u.y & 0xffff0000u);
            float l2 = kS[i].z - __uint_as_float(u.z & 0xffff0000u);
            float l3 = kS[i].w - __uint_as_float(u.w & 0xffff0000u);
            uint32_t off = (uint32_t)(r * STR + c4 * 8);
            *(uint2*)(Kh + off) = make_uint2(h01, h23);
            *(uint2*)(Kl + off) = make_uint2(bf162_bits(l0, l1), bf162_bits(l2, l3));
            float vv[4] = {vS[i].x, vS[i].y, vS[i].z, vS[i].w};
            #pragma unroll
            for (int q = 0; q < 4; q++) {
                int d = c4 * 4 + q;
                uint32_t ub = __float_as_uint(vv[q]);
                unsigned short h = (unsigned short)(ub >> 16);
                float lof = vv[q] - __uint_as_float(ub & 0xffff0000u);
                unsigned short l = __bfloat16_as_ushort(__float2bfloat16_rn(lof));
                uint32_t off2 = (uint32_t)(d * STR + r * 2);
                *(unsigned short*)(Vh + off2) = h;
                *(unsigned short*)(Vl + off2) = l;
            }
        }
    };

    ldKV(0);
    stKV(0);
    __syncthreads();

    uint32_t qh[4][4], qlo[4][4];
    {
        uint32_t qb = dsm_s + (uint32_t)(wid * 16 * STR) + laneA;
        #pragma unroll
        for (int ks = 0; ks < 4; ks++) {
            ldsm_x4(qh[ks],  qb + ks * 32);
            ldsm_x4(qlo[ks], qb + QSZ + ks * 32);
        }
    }

    float o[8][4];
    #pragma unroll
    for (int i = 0; i < 8; i++)
        #pragma unroll
        for (int l = 0; l < 4; l++) o[i][l] = 0.f;
    float mr0 = -INFINITY, mr1 = -INFINITY, lr0 = 0.f, lr1 = 0.f;
    const int row0 = m0 + wid * 16 + gid;
    const int row1 = row0 + 8;

    for (int j = 0; j < ntile; j++) {
        if (j + 1 < ntile) ldKV(j + 1);

        const uint32_t KhS = dsm_s + 2 * QSZ + (uint32_t)((j & 1) * KSTG);
        const uint32_t KlS = KhS + 64 * STR;
        const uint32_t VhS = KhS + 2 * 64 * STR;
        const uint32_t VlS = KhS + 3 * 64 * STR;

        float s[8][4];
        #pragma unroll
        for (int nf = 0; nf < 8; nf++) {
            s[nf][0] = s[nf][1] = s[nf][2] = s[nf][3] = 0.f;
            uint32_t bo = (uint32_t)(nf * 8 * STR) + laneB;
            #pragma unroll
            for (int ks = 0; ks < 4; ks++) {
                uint32_t bh[2], bl[2];
                ldsm_x2(bh, KhS + bo + ks * 32);
                ldsm_x2(bl, KlS + bo + ks * 32);
                mma16816(s[nf], qh[ks][0], qh[ks][1], qh[ks][2], qh[ks][3], bh[0], bh[1]);
                mma16816(s[nf], qh[ks][0], qh[ks][1], qh[ks][2], qh[ks][3], bl[0], bl[1]);
                mma16816(s[nf], qlo[ks][0], qlo[ks][1], qlo[ks][2], qlo[ks][3], bh[0], bh[1]);
            }
        }
        #pragma unroll
        for (int nf = 0; nf < 8; nf++) {
            int c0 = j * 64 + nf * 8 + tig * 2;
            s[nf][0] = (c0     > row0) ? -INFINITY : s[nf][0] * 0.125f;
            s[nf][1] = (c0 + 1 > row0) ? -INFINITY : s[nf][1] * 0.125f;
            s[nf][2] = (c0     > row1) ? -INFINITY : s[nf][2] * 0.125f;
            s[nf][3] = (c0 + 1 > row1) ? -INFINITY : s[nf][3] * 0.125f;
        }
        float mx0 = -INFINITY, mx1 = -INFINITY;
        #pragma unroll
        for (int nf = 0; nf < 8; nf++) {
            mx0 = fmaxf(mx0, fmaxf(s[nf][0], s[nf][1]));
            mx1 = fmaxf(mx1, fmaxf(s[nf][2], s[nf][3]));
        }
        mx0 = fmaxf(mx0, __shfl_xor_sync(0xffffffffu, mx0, 1));
        mx0 = fmaxf(mx0, __shfl_xor_sync(0xffffffffu, mx0, 2));
        mx1 = fmaxf(mx1, __shfl_xor_sync(0xffffffffu, mx1, 1));
        mx1 = fmaxf(mx1, __shfl_xor_sync(0xffffffffu, mx1, 2));
        float mn0 = fmaxf(mr0, mx0), mn1 = fmaxf(mr1, mx1);
        float al0 = expf(mr0 - mn0), al1 = expf(mr1 - mn1);
        float rs0 = 0.f, rs1 = 0.f;
        #pragma unroll
        for (int nf = 0; nf < 8; nf++) {
            s[nf][0] = expf(s[nf][0] - mn0);
            s[nf][1] = expf(s[nf][1] - mn0);
            s[nf][2] = expf(s[nf][2] - mn1);
            s[nf][3] = expf(s[nf][3] - mn1);
            rs0 += s[nf][0] + s[nf][1];
            rs1 += s[nf][2] + s[nf][3];
        }
        rs0 += __shfl_xor_sync(0xffffffffu, rs0, 1);
        rs0 += __shfl_xor_sync(0xffffffffu, rs0, 2);
        rs1 += __shfl_xor_sync(0xffffffffu, rs1, 1);
        rs1 += __shfl_xor_sync(0xffffffffu, rs1, 2);
        lr0 = lr0 * al0 + rs0;
        lr1 = lr1 * al1 + rs1;
        mr0 = mn0; mr1 = mn1;
        #pragma unroll
        for (int df = 0; df < 8; df++) {
            o[df][0] *= al0; o[df][1] *= al0;
            o[df][2] *= al1; o[df][3] *= al1;
        }
        #pragma unroll
        for (int ks = 0; ks < 4; ks++) {
            float* f0 = s[2 * ks];
            float* f1 = s[2 * ks + 1];
            uint32_t ah[4], alo[4];
            ah[0] = hipack(f0[0], f0[1]);  ah[1] = hipack(f0[2], f0[3]);
            ah[2] = hipack(f1[0], f1[1]);  ah[3] = hipack(f1[2], f1[3]);
            alo[0] = bf162_bits(f0[0] - truncbf(f0[0]), f0[1] - truncbf(f0[1]));
            alo[1] = bf162_bits(f0[2] - truncbf(f0[2]), f0[3] - truncbf(f0[3]));
            alo[2] = bf162_bits(f1[0] - truncbf(f1[0]), f1[1] - truncbf(f1[1]));
            alo[3] = bf162_bits(f1[2] - truncbf(f1[2]), f1[3] - truncbf(f1[3]));
            #pragma unroll
            for (int df = 0; df < 8; df++) {
                uint32_t bo = (uint32_t)(df * 8 * STR) + laneB + ks * 32;
                uint32_t bh[2], bl[2];
                ldsm_x2(bh, VhS + bo);
                ldsm_x2(bl, VlS + bo);
                mma16816(o[df], ah[0], ah[1], ah[2], ah[3], bh[0], bh[1]);
                mma16816(o[df], alo[0], alo[1], alo[2], alo[3], bh[0], bh[1]);
                mma16816(o[df], ah[0], ah[1], ah[2], ah[3], bl[0], bl[1]);
            }
        }

        if (j + 1 < ntile) stKV((j + 1) & 1);
        __syncthreads();
    }

    float inv0 = 1.f / lr0, inv1 = 1.f / lr1;
    #pragma unroll
    for (int df = 0; df < 8; df++) {
        int col = head * DHEAD + df * 8 + tig * 2;
        *(float2*)&Octx[(long long)row0 * DMODEL + col] =
            make_float2(o[df][0] * inv0, o[df][1] * inv0);
        *(float2*)&Octx[(long long)row1 * DMODEL + col] =
            make_float2(o[df][2] * inv1, o[df][3] * inv1);
    }
}

// ---------------------------------------------------------------------------
// packT: transpose wk|wq|wv into K-major (pakw[z][n*D+k] = w_z[k*D+n]);
// pack biases. 32x32 smem tiles, grid (32,32,3), block 256 (32x8).
// ---------------------------------------------------------------------------
__global__ void __launch_bounds__(256) packT_k(
    const float* __restrict__ a0, const float* __restrict__ a1, const float* __restrict__ a2,
    const float* __restrict__ b0, const float* __restrict__ b1, const float* __restrict__ b2,
    float* __restrict__ w, float* __restrict__ b)
{
    __shared__ float tile[32][33];
    int z = blockIdx.z;
    const float* src = (z == 0) ? a0 : (z == 1) ? a1 : a2;
    float* dst = w + (size_t)z * DMODEL * DMODEL;
    int bx = blockIdx.x * 32, by = blockIdx.y * 32;
    int tx = threadIdx.x & 31, ty = threadIdx.x >> 5;
    #pragma unroll
    for (int i = 0; i < 32; i += 8)
        tile[ty + i][tx] = src[(size_t)(by + ty + i) * DMODEL + bx + tx];
    __syncthreads();
    #pragma unroll
    for (int i = 0; i < 32; i += 8)
        dst[(size_t)(bx + ty + i) * DMODEL + by + tx] = tile[tx][ty + i];
    if (blockIdx.x == 0 && blockIdx.y == 0) {
        const float* bs = (z == 0) ? b0 : (z == 1) ? b1 : b2;
        for (int i = threadIdx.x; i < DMODEL; i += 256)
            b[z * DMODEL + i] = bs[i];
    }
}

// ---------------------------------------------------------------------------
// biascomb: bcomb[z*D+i] = ipb[z*D+i] + dot(ipw_z[i,:], pakb_z)
// ---------------------------------------------------------------------------
__global__ void __launch_bounds__(256) biascomb_k(
    const float* __restrict__ ipw, const float* __restrict__ ipb,
    const float* __restrict__ pakb, float* __restrict__ bcomb)
{
    int gw = (blockIdx.x * 256 + threadIdx.x) >> 5;
    int lane = threadIdx.x & 31;
    if (gw >= 3 * DMODEL) return;
    int z = gw >> 10, i = gw & (DMODEL - 1);
    const float* wrow = ipw + ((size_t)z * DMODEL + i) * DMODEL;
    const float* bz = pakb + z * DMODEL;
    float s = 0.f;
    for (int k2 = lane; k2 < DMODEL; k2 += 32) s += wrow[k2] * bz[k2];
    #pragma unroll
    for (int o = 16; o; o >>= 1) s += __shfl_down_sync(0xffffffffu, s, o);
    if (lane == 0) bcomb[gw] = s + ipb[gw];
}

// ---------------------------------------------------------------------------
// Block reductions + glue kernels
// ---------------------------------------------------------------------------
__device__ __forceinline__ float blockReduceSum(float val, float* red) {
    int lane = threadIdx.x & 31, wid = threadIdx.x >> 5;
    #pragma unroll
    for (int o = 16; o; o >>= 1) val += __shfl_down_sync(0xffffffffu, val, o);
    __syncthreads();
    if (lane == 0) red[wid] = val;
    __syncthreads();
    if (threadIdx.x < 32) {
        val = (lane < 8) ? red[lane] : 0.f;
        #pragma unroll
        for (int o = 4; o; o >>= 1) val += __shfl_down_sync(0xffffffffu, val, o);
        if (lane == 0) red[0] = val;
    }
    __syncthreads();
    return red[0];
}

__global__ void __launch_bounds__(256) ln_k(const float* __restrict__ x,
                                            const float* __restrict__ w,
                                            const float* __restrict__ b,
                                            float* __restrict__ out) {
    __shared__ float red[8];
    int row = blockIdx.x, tid = threadIdx.x;
    const float* xr = x + (size_t)row * DMODEL;
    float v[4];
    float s = 0.f;
    #pragma unroll
    for (int i = 0; i < 4; i++) { v[i] = xr[tid + i * 256]; s += v[i]; }
    s = blockReduceSum(s, red);
    float mu = s * (1.f / DMODEL);
    float s2 = 0.f;
    #pragma unroll
    for (int i = 0; i < 4; i++) { float d = v[i] - mu; s2 += d * d; }
    s2 = blockReduceSum(s2, red);
    float rstd = rsqrtf(s2 * (1.f / DMODEL) + 1e-5f);
    float* orow = out + (size_t)row * DMODEL;
    #pragma unroll
    for (int i = 0; i < 4; i++) {
        int c = tid + i * 256;
        orow[c] = (v[i] - mu) * rstd * w[c] + b[c];
    }
}

__global__ void __launch_bounds__(512) router_k(const float* __restrict__ h,
                                                const float* __restrict__ rw,
                                                const float* __restrict__ rb,
                                                int* __restrict__ routes,
                                                float* __restrict__ pmax) {
    __shared__ float lg[NEXP];
    int t = blockIdx.x;
    int wid = threadIdx.x >> 5, lane = threadIdx.x & 31;
    const float* hr = h + (size_t)t * DMODEL;
    const float* wr = rw + (size_t)wid * DMODEL;
    float s = 0.f;
    for (int k = lane; k < DMODEL; k += 32) s += hr[k] * wr[k];
    #pragma unroll
    for (int o = 16; o; o >>= 1) s += __shfl_down_sync(0xffffffffu, s, o);
    if (lane == 0) lg[wid] = s + rb[wid];
    __syncthreads();
    if (threadIdx.x == 0) {
        float mx = lg[0]; int arg = 0;
        #pragma unroll
        for (int e = 1; e < NEXP; e++)
            if (lg[e] > mx) { mx = lg[e]; arg = e; }
        float sum = 0.f;
        #pragma unroll
        for (int e = 0; e < NEXP; e++) sum += expf(lg[e] - mx);
        routes[t] = arg;
        pmax[t] = 1.f / sum;
    }
}

__global__ void __launch_bounds__(512) slot_k(const int* __restrict__ routes,
                                              int* __restrict__ slot,
                                              int* __restrict__ keep) {
    __shared__ int sr[NTOK];
    int tid = threadIdx.x;
    for (int i = tid; i < NTOK; i += 512) sr[i] = routes[i];
    __syncthreads();
    int wid = tid >> 5, lane = tid & 31;
    int pos = 0;
    unsigned lmask = (1u << lane) - 1u;
    for (int base = 0; base < NTOK; base += 32) {
        int r = sr[base + lane];
        unsigned m = __ballot_sync(0xffffffffu, r == wid);
        if (r == wid) {
            int p = pos + __popc(m & lmask);
            int kp = (p < CAP) ? 1 : 0;
            keep[base + lane] = kp;
            slot[base + lane] = kp ? (wid * CAP + p) : (NEXP * CAP);
        }
        pos += __popc(m);
    }
}

__global__ void __launch_bounds__(256) gather_k(const float* __restrict__ h,
                                                const int* __restrict__ slot,
                                                const int* __restrict__ keep,
                                                float* __restrict__ buf) {
    int t = blockIdx.x;
    if (!keep[t]) return;
    int s = slot[t];
    const float4* src = (const float4*)(h + (size_t)t * DMODEL);
    float4* dst = (float4*)(buf + (size_t)s * DMODEL);
    dst[threadIdx.x] = src[threadIdx.x];
}

__global__ void __launch_bounds__(256) final_k(const float* __restrict__ x1,
                                               const float* __restrict__ h2,
                                               const float* __restrict__ ye,
                                               const int* __restrict__ slot,
                                               const int* __restrict__ keep,
                                               const float* __restrict__ pmax,
                                               float* __restrict__ out) {
    int t = blockIdx.x;
    float p = pmax[t];
    const float4* ysrc = keep[t]
        ? (const float4*)(ye + (size_t)slot[t] * DMODEL)
        : (const float4*)(h2 + (size_t)t * DMODEL);
    const float4* xs = (const float4*)(x1 + (size_t)t * DMODEL);
    float4 a = xs[threadIdx.x];
    float4 y = ysrc[threadIdx.x];
    float4 o = make_float4(a.x + y.x * p, a.y + y.y * p, a.z + y.z * p, a.w + y.w * p);
    ((float4*)out)[(size_t)t * (DMODEL / 4) + threadIdx.x] = o;
}

// ---------------------------------------------------------------------------
// Launch
// ---------------------------------------------------------------------------
extern "C" void kernel_launch(void* const* d_in, const int* in_sizes, int n_in,
                              void* d_out, int out_size) {
    const float* x    = (const float*)d_in[0];
    const float* wk   = (const float*)d_in[1];
    const float* bk   = (const float*)d_in[2];
    const float* wq   = (const float*)d_in[3];
    const float* bq   = (const float*)d_in[4];
    const float* wv   = (const float*)d_in[5];
    const float* bv   = (const float*)d_in[6];
    const float* ipw  = (const float*)d_in[7];
    const float* ipb  = (const float*)d_in[8];
    const float* opw  = (const float*)d_in[9];
    const float* opb  = (const float*)d_in[10];
    const float* ln1w = (const float*)d_in[11];
    const float* ln1b = (const float*)d_in[12];
    const float* ln2w = (const float*)d_in[13];
    const float* ln2b = (const float*)d_in[14];
    const float* rw   = (const float*)d_in[15];
    const float* rb   = (const float*)d_in[16];
    const float* w1   = (const float*)d_in[17];
    const float* b1   = (const float*)d_in[18];
    const float* w2   = (const float*)d_in[19];
    const float* b2   = (const float*)d_in[20];
    float* out = (float*)d_out;

    void* sp = nullptr;
    cudaGetSymbolAddress(&sp, g_scratch);
    char* base = (char*)sp;
    float* hln    = (float*)(base + OFF_A);
    float* ctx    = (float*)(base + OFF_A);
    float* x1     = (float*)(base + OFF_B);
    float* h2     = (float*)(base + OFF_C);
    float* q      = (float*)(base + OFF_E);
    float* ye     = (float*)(base + OFF_E);
    float* k      = (float*)(base + OFF_F);
    float* v      = (float*)(base + OFF_G);
    float* buf    = (float*)(base + OFF_G);
    float* hexp   = (float*)(base + OFF_HEXP);
    float* pakw   = (float*)(base + OFF_PAKW);
    float* wcmb   = (float*)(base + OFF_WCMB);
    float* pakb   = (float*)(base + OFF_PAKB);
    float* bcmb   = (float*)(base + OFF_BCMB);
    int*   routes = (int*)(base + OFF_ROUTES);
    int*   slot   = (int*)(base + OFF_SLOT);
    int*   keep   = (int*)(base + OFF_KEEP);
    float* pmax   = (float*)(base + OFF_PMAX);

    constexpr long long MAT = (long long)DMODEL * DMODEL;

    auto GP   = mma_gemm<128, 128, true,  false, false>;  // fused proj
    auto GC   = mma_gemm<128, 128, false, false, false>;  // weight combine
    auto GPR  = mma_gemm<128, 128, true,  false, true >;  // out-proj+resid
    auto GW1  = mma_gemm<160, 128, true,  true,  false>;  // w1+relu
    auto GW2  = mma_gemm<160, 128, true,  false, false>;  // w2
    constexpr int SM128 = 2 * (2 * 128 + 2 * 128) * 80;   // 81920
    constexpr int SM160 = 2 * (2 * 160 + 2 * 128) * 80;   // 92160
    constexpr int SMFA  = 2 * 128 * 144 + 2 * 4 * 64 * 144;  // 110592
    cudaFuncSetAttribute(GP,   cudaFuncAttributeMaxDynamicSharedMemorySize, SM128);
    cudaFuncSetAttribute(GC,   cudaFuncAttributeMaxDynamicSharedMemorySize, SM128);
    cudaFuncSetAttribute(GPR,  cudaFuncAttributeMaxDynamicSharedMemorySize, SM128);
    cudaFuncSetAttribute(GW1,  cudaFuncAttributeMaxDynamicSharedMemorySize, SM160);
    cudaFuncSetAttribute(GW2,  cudaFuncAttributeMaxDynamicSharedMemorySize, SM160);
    cudaFuncSetAttribute(fa_k, cudaFuncAttributeMaxDynamicSharedMemorySize, SMFA);

    // ---- LN1 + weight transpose-pack + combine (weight-only work)
    ln_k<<<NTOK, 256>>>(x, ln1w, ln1b, hln);
    dim3 gT(32, 32, 3);
    packT_k<<<gT, 256>>>(wk, wq, wv, bk, bq, bv, pakw, pakb);
    // Wcomb_z = ipw_z @ w_z  (fast NT path: B = w_z^T K-major)
    dim3 gC(DMODEL / 128, DMODEL / 128, 3);
    GC<<<gC, 256, SM128>>>(ipw, pakw, nullptr, nullptr, wcmb,
        DMODEL, DMODEL, DMODEL, DMODEL, DMODEL, DMODEL,
        MAT, MAT, MAT, 0);
    biascomb_k<<<384, 256>>>(ipw, ipb, pakb, bcmb);

    // ---- fused projection: q|k|v = hln @ Wcomb^T + bcomb (one z=3 launch)
    //      (swapped K/Q per reference: z order wk,wq,wv -> q,k,v)
    dim3 gD3(DMODEL / 128, NTOK / 128, 3);
    GP<<<gD3, 256, SM128>>>(hln, wcmb, bcmb, nullptr, q,
        NTOK, DMODEL, DMODEL, DMODEL, DMODEL, DMODEL,
        0, MAT, (long long)NTOK * DMODEL, DMODEL);

    // ---- fused flash attention: one launch, 256 CTAs
    dim3 gFA(NHEAD, NTOK / 128);
    fa_k<<<gFA, 256, SMFA>>>(q, k, v, ctx);

    // ---- x1 = x + ctx @ opw^T + opb
    dim3 gD(DMODEL / 128, NTOK / 128, 1);
    GPR<<<gD, 256, SM128>>>(ctx, opw, opb, x, x1,
        NTOK, DMODEL, DMODEL, DMODEL, DMODEL, DMODEL, 0, 0, 0, 0);

    // ---- LN2
    ln_k<<<NTOK, 256>>>(x1, ln2w, ln2b, h2);

    // ---- router + routing + gather
    router_k<<<NTOK, 512>>>(h2, rw, rb, routes, pmax);
    slot_k<<<1, 512>>>(routes, slot, keep);
    gather_k<<<NTOK, 256>>>(h2, slot, keep, buf);

    // ---- expert FFN layer 1 (relu): single BM=160 launch
    dim3 g1(FEXP / 128, 1, NEXP);
    GW1<<<g1, 256, SM160>>>(buf, w1, b1, nullptr, hexp,
        CAP, FEXP, DMODEL, DMODEL, DMODEL, FEXP,
        (long long)CAP * DMODEL, (long long)FEXP * DMODEL,
        (long long)CAP * FEXP, FEXP);

    // ---- expert FFN layer 2: single BM=160 launch
    dim3 g2(DMODEL / 128, 1, NEXP);
    GW2<<<g2, 256, SM160>>>(hexp, w2, b2, nullptr, ye,
        CAP, DMODEL, FEXP, FEXP, FEXP, DMODEL,
        (long long)CAP * FEXP, (long long)DMODEL * FEXP,
        (long long)CAP * DMODEL, DMODEL);

    // ---- final combine
    final_k<<<NTOK, 256>>>(x1, h2, ye, slot, keep, pmax, out);
}